// round 2
// baseline (speedup 1.0000x reference)
#include <cuda_runtime.h>
#include <math.h>

#define NTOK 768
#define DMODEL 256
#define NHEAD 8
#define HDIM 32

// ---------------- scratch (device globals; no allocations allowed) ----------
__device__ float g_qkv[NTOK * 3 * DMODEL];          // 768 x 768
__device__ float g_scores[NHEAD * NTOK * NTOK];     // 8 x 768 x 768
__device__ float g_o[NTOK * DMODEL];                // attention output (concat heads)
__device__ float g_att[NTOK * DMODEL];              // after out-proj
__device__ float g_Ap[NTOK * DMODEL];               // att @ w1a^T + b1
__device__ float g_Bp[NTOK * DMODEL];               // att @ w1b^T

// ---------------- generic strided SGEMM: C = alpha * A·B^T + bias -----------
// C[m,n] = alpha * sum_k A[m*asr + k*asc] * B[n*bsr + k*bsc]  (+ bias[n])
// batched via blockIdx.z with element-offsets aB/bB/cB.
__global__ void sgemm_strided(const float* __restrict__ A, int asr, int asc, long aB,
                              const float* __restrict__ B, int bsr, int bsc, long bB,
                              const float* __restrict__ bias,
                              float* __restrict__ C, int csr, long cB,
                              int M, int Nc, int K, float alpha)
{
    A += (long)blockIdx.z * aB;
    B += (long)blockIdx.z * bB;
    C += (long)blockIdx.z * cB;

    __shared__ float As[16][65];   // [k][m]
    __shared__ float Bs[16][65];   // [k][n]

    const int m0 = blockIdx.y * 64;
    const int n0 = blockIdx.x * 64;
    const int tid = threadIdx.x;           // 256 threads
    const int tx = tid & 15;
    const int ty = tid >> 4;

    float acc[4][4];
#pragma unroll
    for (int r = 0; r < 4; r++)
#pragma unroll
        for (int c = 0; c < 4; c++) acc[r][c] = 0.f;

    for (int kk = 0; kk < K; kk += 16) {
#pragma unroll
        for (int p = 0; p < 4; p++) {
            int idx = tid + p * 256;       // 0..1023 covers 64x16
            int mm = idx >> 4;
            int k  = idx & 15;
            float va = 0.f, vb = 0.f;
            if (kk + k < K) {
                if (m0 + mm < M)  va = A[(long)(m0 + mm) * asr + (long)(kk + k) * asc];
                if (n0 + mm < Nc) vb = B[(long)(n0 + mm) * bsr + (long)(kk + k) * bsc];
            }
            As[k][mm] = va;
            Bs[k][mm] = vb;
        }
        __syncthreads();
#pragma unroll
        for (int k = 0; k < 16; k++) {
            float a[4], b[4];
#pragma unroll
            for (int r = 0; r < 4; r++) a[r] = As[k][ty * 4 + r];
#pragma unroll
            for (int c = 0; c < 4; c++) b[c] = Bs[k][tx * 4 + c];
#pragma unroll
            for (int r = 0; r < 4; r++)
#pragma unroll
                for (int c = 0; c < 4; c++) acc[r][c] += a[r] * b[c];
        }
        __syncthreads();
    }

#pragma unroll
    for (int r = 0; r < 4; r++) {
        int m = m0 + ty * 4 + r;
        if (m >= M) continue;
#pragma unroll
        for (int c = 0; c < 4; c++) {
            int n = n0 + tx * 4 + c;
            if (n >= Nc) continue;
            float v = alpha * acc[r][c];
            if (bias) v += bias[n];
            C[(long)m * csr + n] = v;
        }
    }
}

// ---------------- rowwise softmax (in place) --------------------------------
__global__ void softmax_rows(float* __restrict__ S, int cols)
{
    long r = blockIdx.x;
    float* row = S + r * (long)cols;
    int t = threadIdx.x;                   // 256 threads
    __shared__ float red[32];

    float mx = -3.4e38f;
    for (int c = t; c < cols; c += 256) mx = fmaxf(mx, row[c]);
#pragma unroll
    for (int o = 16; o > 0; o >>= 1) mx = fmaxf(mx, __shfl_xor_sync(0xffffffffu, mx, o));
    if ((t & 31) == 0) red[t >> 5] = mx;
    __syncthreads();
    float m2 = red[0];
#pragma unroll
    for (int w = 1; w < 8; w++) m2 = fmaxf(m2, red[w]);
    __syncthreads();

    float s = 0.f;
    for (int c = t; c < cols; c += 256) {
        float e = __expf(row[c] - m2);
        row[c] = e;
        s += e;
    }
#pragma unroll
    for (int o = 16; o > 0; o >>= 1) s += __shfl_xor_sync(0xffffffffu, s, o);
    if ((t & 31) == 0) red[t >> 5] = s;
    __syncthreads();
    float tot = 0.f;
#pragma unroll
    for (int w = 0; w < 8; w++) tot += red[w];
    float inv = 1.f / tot;
    for (int c = t; c < cols; c += 256) row[c] *= inv;
}

// ---------------- fused per-pair MLP ---------------------------------------
// One block: pair tile = (fixed i) x (64 consecutive j).
// layer1 (cubic term GEMM 64x256x256) + adds + relu + LN + 256->128->64->32->1
// all in shared memory. Intermediates stored transposed: hT[feature][pair].
#define PITCH  72    // pair-tile pitch (64 rows padded; 16B aligned, 4-way banks)
#define WPITCH 257   // weight staging pitch (conflict-free scalar access)

// smem layout (floats)
#define OFF_HSMT 0
#define OFF_H2T  (OFF_HSMT + 256 * PITCH)
#define OFF_H3T  (OFF_H2T  + 128 * PITCH)
#define OFF_H4T  (OFF_H3T  +  64 * PITCH)
#define OFF_PST  (OFF_H4T  +  32 * PITCH)
#define OFF_WS   (OFF_PST  +  32 * PITCH)
#define OFF_SAI  (OFF_WS   +  32 * WPITCH)
#define OFF_SAP  (OFF_SAI  + 256)
#define OFF_SW0  (OFF_SAP  + 256)
#define OFF_SW1  (OFF_SW0  + 256)
#define OFF_SW2  (OFF_SW1  + 256)
#define OFF_SLG  (OFF_SW2  + 256)
#define OFF_SLB  (OFF_SLG  + 256)
#define OFF_SW5  (OFF_SLB  + 256)
#define OFF_SSX  (OFF_SW5  + 32)
#define OFF_SSYA (OFF_SSX  + 64)
#define OFF_SSYS (OFF_SSYA + 64)
#define SMEM_FLOATS (OFF_SSYS + 64)
#define SMEM_BYTES  (SMEM_FLOATS * 4)

__global__ __launch_bounds__(512, 1) void fused_pairs(
    const float* __restrict__ att, const float* __restrict__ boxes,
    const float* __restrict__ w1,
    const float* __restrict__ Ap, const float* __restrict__ Bp,
    const float* __restrict__ lng, const float* __restrict__ lnb,
    const float* __restrict__ w2, const float* __restrict__ b2,
    const float* __restrict__ w3, const float* __restrict__ b3,
    const float* __restrict__ w4, const float* __restrict__ b4,
    const float* __restrict__ w5, const float* __restrict__ b5,
    float* __restrict__ out)
{
    extern __shared__ float sm[];
    float* hsmT = sm + OFF_HSMT;
    float* h2T  = sm + OFF_H2T;
    float* h3T  = sm + OFF_H3T;
    float* h4T  = sm + OFF_H4T;
    float* PsT  = sm + OFF_PST;
    float* Ws   = sm + OFF_WS;
    float* sAi  = sm + OFF_SAI;
    float* sAp  = sm + OFF_SAP;
    float* sW0  = sm + OFF_SW0;
    float* sW1  = sm + OFF_SW1;
    float* sW2  = sm + OFF_SW2;
    float* sLg  = sm + OFF_SLG;
    float* sLb  = sm + OFF_SLB;
    float* sW5  = sm + OFF_SW5;
    float* sSx  = sm + OFF_SSX;
    float* sSyA = sm + OFF_SSYA;
    float* sSyS = sm + OFF_SSYS;

    const int i  = blockIdx.y;
    const int j0 = blockIdx.x * 64;
    const int t  = threadIdx.x;          // 512 threads

    // ---- stage block invariants
    for (int k = t; k < 256; k += 512) {
        sAi[k] = att[i * 256 + k];
        sAp[k] = Ap[i * 256 + k];
        sW0[k] = w1[k * 771 + 768];
        sW1[k] = w1[k * 771 + 769];
        sW2[k] = w1[k * 771 + 770];
        sLg[k] = lng[k];
        sLb[k] = lnb[k];
    }
    if (t < 32) sW5[t] = w5[t];
    if (t < 64) {
        int j = j0 + t;
        float bxi = boxes[i * 4 + 0], byi = boxes[i * 4 + 1];
        float dy = byi - boxes[j * 4 + 1];
        sSx[t]  = fabsf(bxi - boxes[j * 4 + 0]);
        sSyA[t] = fabsf(dy);
        sSyS[t] = dy;
    }
    __syncthreads();

    const int tx = t & 31;   // 0..31 -> output-feature groups
    const int ty = t >> 5;   // 0..15 -> pair-row groups (4 rows each)
    const int dd = t & 31;   // staging: reduction index
    const int kq = t >> 5;   // staging: feature index base

    // ================= layer 1: cubic term GEMM (64 pairs x 256 feats, K=256)
    float acc[4][8];
#pragma unroll
    for (int r = 0; r < 4; r++)
#pragma unroll
        for (int c = 0; c < 8; c++) acc[r][c] = 0.f;

    for (int kk = 0; kk < 256; kk += 32) {
        // P[d][j] = att[j0+j, kk+d] * att[i, kk+d]
#pragma unroll
        for (int p = 0; p < 4; p++) {
            int j = kq + 16 * p;
            PsT[dd * PITCH + j] = att[(j0 + j) * 256 + kk + dd] * sAi[kk + dd];
        }
        // Ws[d][k] = w1c[k, kk+d]   (w1 cols 512..767)
#pragma unroll
        for (int p = 0; p < 16; p++) {
            int k = kq + 16 * p;
            Ws[dd * WPITCH + k] = w1[k * 771 + 512 + kk + dd];
        }
        __syncthreads();
#pragma unroll
        for (int d2 = 0; d2 < 32; d2++) {
            float4 a4 = *(const float4*)&PsT[d2 * PITCH + ty * 4];
#pragma unroll
            for (int c = 0; c < 8; c++) {
                float b = Ws[d2 * WPITCH + tx + 32 * c];
                acc[0][c] += a4.x * b;
                acc[1][c] += a4.y * b;
                acc[2][c] += a4.z * b;
                acc[3][c] += a4.w * b;
            }
        }
        __syncthreads();
    }

    // ---- epilogue: + Ap[i] (incl b1) + Bp[j] + spatial, relu, store transposed
#pragma unroll
    for (int r = 0; r < 4; r++) {
        int jr = ty * 4 + r;
        int j  = j0 + jr;
        float sx = sSx[jr], sya = sSyA[jr], sys = sSyS[jr];
#pragma unroll
        for (int c = 0; c < 8; c++) {
            int k = tx + 32 * c;
            float v = acc[r][c] + sAp[k] + Bp[j * 256 + k]
                    + sx * sW0[k] + sya * sW1[k] + sys * sW2[k];
            hsmT[k * PITCH + jr] = fmaxf(v, 0.f);
        }
    }
    __syncthreads();

    // ================= layernorm per pair over 256 features
    {
        int warp = t >> 5, lane = t & 31;
#pragma unroll
        for (int rj = 0; rj < 4; rj++) {
            int jr = warp * 4 + rj;
            float v[8];
            float s = 0.f, s2 = 0.f;
#pragma unroll
            for (int q = 0; q < 8; q++) {
                v[q] = hsmT[(lane + 32 * q) * PITCH + jr];
                s  += v[q];
                s2 += v[q] * v[q];
            }
#pragma unroll
            for (int o = 16; o > 0; o >>= 1) {
                s  += __shfl_xor_sync(0xffffffffu, s,  o);
                s2 += __shfl_xor_sync(0xffffffffu, s2, o);
            }
            float mu  = s * (1.f / 256.f);
            float var = s2 * (1.f / 256.f) - mu * mu;
            float rs  = rsqrtf(var + 1e-5f);
#pragma unroll
            for (int q = 0; q < 8; q++) {
                int k = lane + 32 * q;
                hsmT[k * PITCH + jr] = (v[q] - mu) * rs * sLg[k] + sLb[k];
            }
        }
    }
    __syncthreads();

    // ================= layer 2: 256 -> 128
    float acc2[4][4];
#pragma unroll
    for (int r = 0; r < 4; r++)
#pragma unroll
        for (int c = 0; c < 4; c++) acc2[r][c] = 0.f;

    for (int kk = 0; kk < 256; kk += 32) {
#pragma unroll
        for (int p = 0; p < 8; p++) {
            int k2 = kq + 16 * p;
            Ws[dd * WPITCH + k2] = w2[k2 * 256 + kk + dd];
        }
        __syncthreads();
#pragma unroll
        for (int d2 = 0; d2 < 32; d2++) {
            float4 a4 = *(const float4*)&hsmT[(kk + d2) * PITCH + ty * 4];
#pragma unroll
            for (int c = 0; c < 4; c++) {
                float b = Ws[d2 * WPITCH + tx + 32 * c];
                acc2[0][c] += a4.x * b;
                acc2[1][c] += a4.y * b;
                acc2[2][c] += a4.z * b;
                acc2[3][c] += a4.w * b;
            }
        }
        __syncthreads();
    }
#pragma unroll
    for (int r = 0; r < 4; r++) {
        int jr = ty * 4 + r;
#pragma unroll
        for (int c = 0; c < 4; c++) {
            int k2 = tx + 32 * c;
            float v = acc2[r][c] + b2[k2];
            h2T[k2 * PITCH + jr] = fmaxf(v, 0.f);
        }
    }
    __syncthreads();

    // ================= layer 3: 128 -> 64
    float acc3[4][2];
#pragma unroll
    for (int r = 0; r < 4; r++) { acc3[r][0] = 0.f; acc3[r][1] = 0.f; }

    for (int kk = 0; kk < 128; kk += 32) {
#pragma unroll
        for (int p = 0; p < 4; p++) {
            int k3 = kq + 16 * p;
            Ws[dd * WPITCH + k3] = w3[k3 * 128 + kk + dd];
        }
        __syncthreads();
#pragma unroll
        for (int d2 = 0; d2 < 32; d2++) {
            float4 a4 = *(const float4*)&h2T[(kk + d2) * PITCH + ty * 4];
#pragma unroll
            for (int c = 0; c < 2; c++) {
                float b = Ws[d2 * WPITCH + tx + 32 * c];
                acc3[0][c] += a4.x * b;
                acc3[1][c] += a4.y * b;
                acc3[2][c] += a4.z * b;
                acc3[3][c] += a4.w * b;
            }
        }
        __syncthreads();
    }
#pragma unroll
    for (int r = 0; r < 4; r++) {
        int jr = ty * 4 + r;
#pragma unroll
        for (int c = 0; c < 2; c++) {
            int k3 = tx + 32 * c;
            float v = acc3[r][c] + b3[k3];
            h3T[k3 * PITCH + jr] = fmaxf(v, 0.f);
        }
    }
    __syncthreads();

    // ================= layer 4: 64 -> 32
    float acc4[4];
#pragma unroll
    for (int r = 0; r < 4; r++) acc4[r] = 0.f;

    for (int kk = 0; kk < 64; kk += 32) {
#pragma unroll
        for (int p = 0; p < 2; p++) {
            int k4 = kq + 16 * p;
            Ws[dd * WPITCH + k4] = w4[k4 * 64 + kk + dd];
        }
        __syncthreads();
#pragma unroll
        for (int d2 = 0; d2 < 32; d2++) {
            float4 a4 = *(const float4*)&h3T[(kk + d2) * PITCH + ty * 4];
            float b = Ws[d2 * WPITCH + tx];
            acc4[0] += a4.x * b;
            acc4[1] += a4.y * b;
            acc4[2] += a4.z * b;
            acc4[3] += a4.w * b;
        }
        __syncthreads();
    }
#pragma unroll
    for (int r = 0; r < 4; r++) {
        int jr = ty * 4 + r;
        float v = acc4[r] + b4[tx];
        h4T[tx * PITCH + jr] = fmaxf(v, 0.f);
    }
    __syncthreads();

    // ================= layer 5: 32 -> 1 + diagonal mask + write
    if (t < 64) {
        int j = j0 + t;
        float s = b5[0];
#pragma unroll
        for (int k = 0; k < 32; k++) s += h4T[k * PITCH + t] * sW5[k];
        out[i * 768 + j] = (j == i) ? -1000000000.0f : s;
    }
}

// ---------------- host launch ----------------------------------------------
extern "C" void kernel_launch(void* const* d_in, const int* in_sizes, int n_in,
                              void* d_out, int out_size)
{
    (void)in_sizes; (void)n_in; (void)out_size;
    const float* features = (const float*)d_in[0];
    const float* boxes    = (const float*)d_in[1];
    const float* in_w     = (const float*)d_in[2];
    const float* in_b     = (const float*)d_in[3];
    const float* out_w    = (const float*)d_in[4];
    const float* out_b    = (const float*)d_in[5];
    const float* w1       = (const float*)d_in[6];
    const float* b1       = (const float*)d_in[7];
    const float* lng      = (const float*)d_in[8];
    const float* lnb      = (const float*)d_in[9];
    const float* w2       = (const float*)d_in[10];
    const float* b2       = (const float*)d_in[11];
    const float* w3       = (const float*)d_in[12];
    const float* b3       = (const float*)d_in[13];
    const float* w4       = (const float*)d_in[14];
    const float* b4       = (const float*)d_in[15];
    const float* w5       = (const float*)d_in[16];
    const float* b5       = (const float*)d_in[17];
    float* out = (float*)d_out;

    float *qkv, *scores, *o, *att, *Apb, *Bpb;
    cudaGetSymbolAddress((void**)&qkv,    g_qkv);
    cudaGetSymbolAddress((void**)&scores, g_scores);
    cudaGetSymbolAddress((void**)&o,      g_o);
    cudaGetSymbolAddress((void**)&att,    g_att);
    cudaGetSymbolAddress((void**)&Apb,    g_Ap);
    cudaGetSymbolAddress((void**)&Bpb,    g_Bp);

    // qkv = features @ in_proj_w^T + in_proj_b          (768 x 768, K=256)
    sgemm_strided<<<dim3(12, 12), 256>>>(features, 256, 1, 0,
                                         in_w, 256, 1, 0,
                                         in_b, qkv, 768, 0,
                                         768, 768, 256, 1.f);
    // scores[h] = q_h @ k_h^T / sqrt(32)                (768 x 768, K=32, 8 heads)
    sgemm_strided<<<dim3(12, 12, 8), 256>>>(qkv, 768, 1, 32,
                                            qkv + 256, 768, 1, 32,
                                            nullptr, scores, 768, 768L * 768,
                                            768, 768, 32, 0.17677669529663687f);
    // softmax over last axis
    softmax_rows<<<NHEAD * NTOK, 256>>>(scores, 768);
    // o[:, h*32+d] = attn_h @ v_h                        (768 x 32, K=768, 8 heads)
    sgemm_strided<<<dim3(1, 12, 8), 256>>>(scores, 768, 1, 768L * 768,
                                           qkv + 512, 1, 768, 32,
                                           nullptr, o, 256, 32,
                                           768, 32, 768, 1.f);
    // att = o @ out_proj_w^T + out_proj_b               (768 x 256, K=256)
    sgemm_strided<<<dim3(4, 12), 256>>>(o, 256, 1, 0,
                                        out_w, 256, 1, 0,
                                        out_b, att, 256, 0,
                                        768, 256, 256, 1.f);
    // Ap = att @ w1[:, 0:256]^T + b1 ;  Bp = att @ w1[:, 256:512]^T
    sgemm_strided<<<dim3(4, 12), 256>>>(att, 256, 1, 0,
                                        w1, 771, 1, 0,
                                        b1, Apb, 256, 0,
                                        768, 256, 256, 1.f);
    sgemm_strided<<<dim3(4, 12), 256>>>(att, 256, 1, 0,
                                        w1 + 256, 771, 1, 0,
                                        nullptr, Bpb, 256, 0,
                                        768, 256, 256, 1.f);

    // fused all-pairs MLP: grid = (j-tiles of 64) x (i)
    cudaFuncSetAttribute(fused_pairs, cudaFuncAttributeMaxDynamicSharedMemorySize,
                         SMEM_BYTES);
    fused_pairs<<<dim3(12, 768), 512, SMEM_BYTES>>>(
        att, boxes, w1, Apb, Bpb, lng, lnb,
        w2, b2, w3, b3, w4, b4, w5, b5, out);
}

// round 3
// speedup vs baseline: 2.7982x; 2.7982x over previous
#include <cuda_runtime.h>
#include <cuda_bf16.h>
#include <math.h>

#define NTOK 768
#define DMODEL 256
#define NHEAD 8

// ---------------- scratch (device globals; no allocations allowed) ----------
__device__ float g_qkv[NTOK * 3 * DMODEL];
__device__ float g_scores[NHEAD * NTOK * NTOK];
__device__ float g_o[NTOK * DMODEL];
__device__ float g_att[NTOK * DMODEL];
__device__ float g_Ap[NTOK * DMODEL];
__device__ float g_Bp[NTOK * DMODEL];
__device__ __nv_bfloat16 g_w1c_bf[256 * 256];
__device__ __nv_bfloat16 g_w2_bf[128 * 256];
__device__ __nv_bfloat16 g_w3_bf[64 * 128];
__device__ __nv_bfloat16 g_w4_bf[32 * 64];

// ---------------- generic strided SGEMM: C = alpha * A·B^T + bias -----------
__global__ void sgemm_strided(const float* __restrict__ A, int asr, int asc, long aB,
                              const float* __restrict__ B, int bsr, int bsc, long bB,
                              const float* __restrict__ bias,
                              float* __restrict__ C, int csr, long cB,
                              int M, int Nc, int K, float alpha)
{
    A += (long)blockIdx.z * aB;
    B += (long)blockIdx.z * bB;
    C += (long)blockIdx.z * cB;

    __shared__ float As[16][65];
    __shared__ float Bs[16][65];

    const int m0 = blockIdx.y * 64;
    const int n0 = blockIdx.x * 64;
    const int tid = threadIdx.x;
    const int tx = tid & 15;
    const int ty = tid >> 4;

    float acc[4][4];
#pragma unroll
    for (int r = 0; r < 4; r++)
#pragma unroll
        for (int c = 0; c < 4; c++) acc[r][c] = 0.f;

    for (int kk = 0; kk < K; kk += 16) {
#pragma unroll
        for (int p = 0; p < 4; p++) {
            int idx = tid + p * 256;
            int mm = idx >> 4;
            int k  = idx & 15;
            float va = 0.f, vb = 0.f;
            if (kk + k < K) {
                if (m0 + mm < M)  va = A[(long)(m0 + mm) * asr + (long)(kk + k) * asc];
                if (n0 + mm < Nc) vb = B[(long)(n0 + mm) * bsr + (long)(kk + k) * bsc];
            }
            As[k][mm] = va;
            Bs[k][mm] = vb;
        }
        __syncthreads();
#pragma unroll
        for (int k = 0; k < 16; k++) {
            float a[4], b[4];
#pragma unroll
            for (int r = 0; r < 4; r++) a[r] = As[k][ty * 4 + r];
#pragma unroll
            for (int c = 0; c < 4; c++) b[c] = Bs[k][tx * 4 + c];
#pragma unroll
            for (int r = 0; r < 4; r++)
#pragma unroll
                for (int c = 0; c < 4; c++) acc[r][c] += a[r] * b[c];
        }
        __syncthreads();
    }

#pragma unroll
    for (int r = 0; r < 4; r++) {
        int m = m0 + ty * 4 + r;
        if (m >= M) continue;
#pragma unroll
        for (int c = 0; c < 4; c++) {
            int n = n0 + tx * 4 + c;
            if (n >= Nc) continue;
            float v = alpha * acc[r][c];
            if (bias) v += bias[n];
            C[(long)m * csr + n] = v;
        }
    }
}

// ---------------- rowwise softmax (in place) --------------------------------
__global__ void softmax_rows(float* __restrict__ S, int cols)
{
    long r = blockIdx.x;
    float* row = S + r * (long)cols;
    int t = threadIdx.x;
    __shared__ float red[32];

    float mx = -3.4e38f;
    for (int c = t; c < cols; c += 256) mx = fmaxf(mx, row[c]);
#pragma unroll
    for (int o = 16; o > 0; o >>= 1) mx = fmaxf(mx, __shfl_xor_sync(0xffffffffu, mx, o));
    if ((t & 31) == 0) red[t >> 5] = mx;
    __syncthreads();
    float m2 = red[0];
#pragma unroll
    for (int w = 1; w < 8; w++) m2 = fmaxf(m2, red[w]);
    __syncthreads();

    float s = 0.f;
    for (int c = t; c < cols; c += 256) {
        float e = __expf(row[c] - m2);
        row[c] = e;
        s += e;
    }
#pragma unroll
    for (int o = 16; o > 0; o >>= 1) s += __shfl_xor_sync(0xffffffffu, s, o);
    if ((t & 31) == 0) red[t >> 5] = s;
    __syncthreads();
    float tot = 0.f;
#pragma unroll
    for (int w = 0; w < 8; w++) tot += red[w];
    float inv = 1.f / tot;
    for (int c = t; c < cols; c += 256) row[c] *= inv;
}

// ---------------- weight conversion to bf16 ---------------------------------
__global__ void convert_weights(const float* __restrict__ w1,
                                const float* __restrict__ w2,
                                const float* __restrict__ w3,
                                const float* __restrict__ w4)
{
    int t = blockIdx.x * 256 + threadIdx.x;
    if (t < 65536) {
        int n = t >> 8, d = t & 255;
        g_w1c_bf[t] = __float2bfloat16_rn(w1[n * 771 + 512 + d]);
    }
    if (t < 32768) g_w2_bf[t] = __float2bfloat16_rn(w2[t]);
    if (t < 8192)  g_w3_bf[t] = __float2bfloat16_rn(w3[t]);
    if (t < 2048)  g_w4_bf[t] = __float2bfloat16_rn(w4[t]);
}

// ---------------- fused all-pairs MLP with mma.sync bf16 --------------------
// Block: pair tile = (fixed i) x (128 consecutive j). 256 threads = 8 warps,
// warp w owns pair rows [w*16, w*16+16). All layers via m16n8k16 bf16 HMMA.
// SMEM pitches (u32): 132 / 68 / 36 / 20 — all ≡ 4 (mod 32) -> conflict-free.

#define U32_P  16896                 // 128 x 132
#define U32_H1 16896                 // 128 x 132
#define U32_WS 8448                  // 64 x 132 (max weight stage)
#define SM_U32_TOTAL (U32_P + U32_H1 + U32_WS)
#define SM_F32_EXTRA 2432
#define SMEM_BYTES (SM_U32_TOTAL * 4 + SM_F32_EXTRA * 4)

__device__ __forceinline__ void mma_bf16(float* c, unsigned a0, unsigned a1,
                                         unsigned a2, unsigned a3,
                                         unsigned b0, unsigned b1)
{
    asm volatile(
        "mma.sync.aligned.m16n8k16.row.col.f32.bf16.bf16.f32 "
        "{%0,%1,%2,%3}, {%4,%5,%6,%7}, {%8,%9}, {%0,%1,%2,%3};"
        : "+f"(c[0]), "+f"(c[1]), "+f"(c[2]), "+f"(c[3])
        : "r"(a0), "r"(a1), "r"(a2), "r"(a3), "r"(b0), "r"(b1));
}

__device__ __forceinline__ unsigned pack_bf16(float a, float b)
{
    __nv_bfloat162 h;
    h.x = __float2bfloat16_rn(a);
    h.y = __float2bfloat16_rn(b);
    return *reinterpret_cast<unsigned*>(&h);
}

__device__ __forceinline__ float2 unpack_bf16(unsigned u)
{
    __nv_bfloat162 h = *reinterpret_cast<__nv_bfloat162*>(&u);
    return make_float2(__bfloat162float(h.x), __bfloat162float(h.y));
}

__global__ __launch_bounds__(256, 1) void fused_pairs_mma(
    const float* __restrict__ att, const float* __restrict__ boxes,
    const float* __restrict__ w1,
    const float* __restrict__ Ap, const float* __restrict__ Bp,
    const float* __restrict__ lng, const float* __restrict__ lnb,
    const float* __restrict__ b2, const float* __restrict__ b3,
    const float* __restrict__ b4,
    const float* __restrict__ w5, const float* __restrict__ b5,
    float* __restrict__ out)
{
    extern __shared__ unsigned sm[];
    unsigned* P  = sm;                    // layer1 A tile (bf16 pairs), pitch 132
    unsigned* H1 = sm + U32_P;            // layer1/2 activations, pitch 132
    unsigned* WS = sm + U32_P + U32_H1;   // staged weights
    unsigned* H2 = P;                     // pitch 68 (P dead after layer1)
    unsigned* H3 = P + 8704;              // pitch 36
    unsigned* H4 = H1;                    // pitch 20 (H1 dead after layer2)
    float* fsm = (float*)(sm + SM_U32_TOTAL);
    float* sAi  = fsm;          // 256
    float* sAp  = fsm + 256;    // 256
    float* sW0  = fsm + 512;    // 256
    float* sW1  = fsm + 768;    // 256
    float* sW2  = fsm + 1024;   // 256
    float* sLg  = fsm + 1280;   // 256
    float* sLb  = fsm + 1536;   // 256
    float* sB2  = fsm + 1792;   // 128
    float* sB3  = fsm + 1920;   // 64
    float* sB4  = fsm + 1984;   // 32
    float* sW5  = fsm + 2016;   // 32
    float* sSx  = fsm + 2048;   // 128
    float* sSyA = fsm + 2176;   // 128
    float* sSyS = fsm + 2304;   // 128

    const int i  = blockIdx.y;
    const int j0 = blockIdx.x * 128;
    const int t  = threadIdx.x;
    const int warp = t >> 5;
    const int lane = t & 31;
    const int g    = lane >> 2;   // 0..7
    const int tig  = lane & 3;    // 0..3
    const int m0   = warp * 16;

    // ---- stage block invariants
    for (int k = t; k < 256; k += 256) {
        sAi[k] = att[i * 256 + k];
        sAp[k] = Ap[i * 256 + k];
        sW0[k] = w1[k * 771 + 768];
        sW1[k] = w1[k * 771 + 769];
        sW2[k] = w1[k * 771 + 770];
        sLg[k] = lng[k];
        sLb[k] = lnb[k];
    }
    if (t < 128) sB2[t] = b2[t];
    if (t < 64)  sB3[t] = b3[t];
    if (t < 32)  { sB4[t] = b4[t]; sW5[t] = w5[t]; }
    if (t < 128) {
        int j = j0 + t;
        float bxi = boxes[i * 4 + 0], byi = boxes[i * 4 + 1];
        float dy = byi - boxes[j * 4 + 1];
        sSx[t]  = fabsf(bxi - boxes[j * 4 + 0]);
        sSyA[t] = fabsf(dy);
        sSyS[t] = dy;
    }
    __syncthreads();

    // ---- build P[m][d] = att[j0+m, d] * att[i, d]   (bf16 pairs)
    for (int idx = t; idx < 128 * 128; idx += 256) {
        int m = idx >> 7, c = idx & 127;
        float2 aj = *(const float2*)&att[(j0 + m) * 256 + 2 * c];
        P[m * 132 + c] = pack_bf16(aj.x * sAi[2 * c], aj.y * sAi[2 * c + 1]);
    }

    const int mr0 = m0 + g, mr1 = m0 + 8 + g;
    const int jg0 = j0 + mr0, jg1 = j0 + mr1;

    // ================= layer 1: 128 x 256 x 256 (cubic term) =================
    for (int nc = 0; nc < 4; nc++) {
        const int n0 = nc * 64;
        __syncthreads();
        {
            const unsigned* wsrc = (const unsigned*)g_w1c_bf + n0 * 128;
            for (int idx = t; idx < 64 * 128; idx += 256) {
                int r = idx >> 7, c = idx & 127;
                WS[r * 132 + c] = wsrc[r * 128 + c];
            }
        }
        __syncthreads();

        float acc[8][4];
#pragma unroll
        for (int nt = 0; nt < 8; nt++)
#pragma unroll
            for (int q = 0; q < 4; q++) acc[nt][q] = 0.f;

#pragma unroll 4
        for (int ks = 0; ks < 16; ks++) {
            int kc = ks * 8 + tig;
            unsigned a0 = P[mr0 * 132 + kc];
            unsigned a1 = P[mr1 * 132 + kc];
            unsigned a2 = P[mr0 * 132 + kc + 4];
            unsigned a3 = P[mr1 * 132 + kc + 4];
#pragma unroll
            for (int nt = 0; nt < 8; nt++) {
                unsigned b0 = WS[(nt * 8 + g) * 132 + kc];
                unsigned b1 = WS[(nt * 8 + g) * 132 + kc + 4];
                mma_bf16(acc[nt], a0, a1, a2, a3, b0, b1);
            }
        }

        // epilogue: + Ap + Bp + spatial, relu, pack to H1
        float sx0 = sSx[mr0], sya0 = sSyA[mr0], sys0 = sSyS[mr0];
        float sx1 = sSx[mr1], sya1 = sSyA[mr1], sys1 = sSyS[mr1];
#pragma unroll
        for (int nt = 0; nt < 8; nt++) {
            int n = n0 + nt * 8 + 2 * tig;
            float c0a = sAp[n]     + sx0 * sW0[n]     + sya0 * sW1[n]     + sys0 * sW2[n];
            float c0b = sAp[n + 1] + sx0 * sW0[n + 1] + sya0 * sW1[n + 1] + sys0 * sW2[n + 1];
            float c1a = sAp[n]     + sx1 * sW0[n]     + sya1 * sW1[n]     + sys1 * sW2[n];
            float c1b = sAp[n + 1] + sx1 * sW0[n + 1] + sya1 * sW1[n + 1] + sys1 * sW2[n + 1];
            float v00 = acc[nt][0] + c0a + Bp[jg0 * 256 + n];
            float v01 = acc[nt][1] + c0b + Bp[jg0 * 256 + n + 1];
            float v10 = acc[nt][2] + c1a + Bp[jg1 * 256 + n];
            float v11 = acc[nt][3] + c1b + Bp[jg1 * 256 + n + 1];
            H1[mr0 * 132 + (n >> 1)] = pack_bf16(fmaxf(v00, 0.f), fmaxf(v01, 0.f));
            H1[mr1 * 132 + (n >> 1)] = pack_bf16(fmaxf(v10, 0.f), fmaxf(v11, 0.f));
        }
    }
    __syncwarp();

    // ================= layernorm per pair (warp handles its own 16 rows) ====
    for (int r = 0; r < 16; r++) {
        int m = m0 + r;
        float2 v[4];
        float s = 0.f, s2 = 0.f;
#pragma unroll
        for (int q = 0; q < 4; q++) {
            v[q] = unpack_bf16(H1[m * 132 + lane + 32 * q]);
            s  += v[q].x + v[q].y;
            s2 += v[q].x * v[q].x + v[q].y * v[q].y;
        }
#pragma unroll
        for (int o = 16; o > 0; o >>= 1) {
            s  += __shfl_xor_sync(0xffffffffu, s,  o);
            s2 += __shfl_xor_sync(0xffffffffu, s2, o);
        }
        float mu  = s * (1.f / 256.f);
        float var = s2 * (1.f / 256.f) - mu * mu;
        float rs  = rsqrtf(var + 1e-5f);
#pragma unroll
        for (int q = 0; q < 4; q++) {
            int k = 2 * (lane + 32 * q);
            float nx = (v[q].x - mu) * rs * sLg[k]     + sLb[k];
            float ny = (v[q].y - mu) * rs * sLg[k + 1] + sLb[k + 1];
            H1[m * 132 + lane + 32 * q] = pack_bf16(nx, ny);
        }
    }

    // ================= layer 2: 128 x 128 x 256 ==============================
    for (int nc = 0; nc < 2; nc++) {
        const int n0 = nc * 64;
        __syncthreads();
        {
            const unsigned* wsrc = (const unsigned*)g_w2_bf + n0 * 128;
            for (int idx = t; idx < 64 * 128; idx += 256) {
                int r = idx >> 7, c = idx & 127;
                WS[r * 132 + c] = wsrc[r * 128 + c];
            }
        }
        __syncthreads();

        float acc[8][4];
#pragma unroll
        for (int nt = 0; nt < 8; nt++)
#pragma unroll
            for (int q = 0; q < 4; q++) acc[nt][q] = 0.f;

#pragma unroll 4
        for (int ks = 0; ks < 16; ks++) {
            int kc = ks * 8 + tig;
            unsigned a0 = H1[mr0 * 132 + kc];
            unsigned a1 = H1[mr1 * 132 + kc];
            unsigned a2 = H1[mr0 * 132 + kc + 4];
            unsigned a3 = H1[mr1 * 132 + kc + 4];
#pragma unroll
            for (int nt = 0; nt < 8; nt++) {
                unsigned b0 = WS[(nt * 8 + g) * 132 + kc];
                unsigned b1 = WS[(nt * 8 + g) * 132 + kc + 4];
                mma_bf16(acc[nt], a0, a1, a2, a3, b0, b1);
            }
        }
        __syncthreads();   // H2 aliases P; also guards WS restage
#pragma unroll
        for (int nt = 0; nt < 8; nt++) {
            int n = n0 + nt * 8 + 2 * tig;
            float v00 = acc[nt][0] + sB2[n];
            float v01 = acc[nt][1] + sB2[n + 1];
            float v10 = acc[nt][2] + sB2[n];
            float v11 = acc[nt][3] + sB2[n + 1];
            H2[mr0 * 68 + (n >> 1)] = pack_bf16(fmaxf(v00, 0.f), fmaxf(v01, 0.f));
            H2[mr1 * 68 + (n >> 1)] = pack_bf16(fmaxf(v10, 0.f), fmaxf(v11, 0.f));
        }
    }
    __syncthreads();

    // ================= layer 3: 128 x 64 x 128 ===============================
    {
        const unsigned* wsrc = (const unsigned*)g_w3_bf;
        for (int idx = t; idx < 64 * 64; idx += 256) {
            int r = idx >> 6, c = idx & 63;
            WS[r * 68 + c] = wsrc[r * 64 + c];
        }
        __syncthreads();

        float acc[8][4];
#pragma unroll
        for (int nt = 0; nt < 8; nt++)
#pragma unroll
            for (int q = 0; q < 4; q++) acc[nt][q] = 0.f;

#pragma unroll
        for (int ks = 0; ks < 8; ks++) {
            int kc = ks * 8 + tig;
            unsigned a0 = H2[mr0 * 68 + kc];
            unsigned a1 = H2[mr1 * 68 + kc];
            unsigned a2 = H2[mr0 * 68 + kc + 4];
            unsigned a3 = H2[mr1 * 68 + kc + 4];
#pragma unroll
            for (int nt = 0; nt < 8; nt++) {
                unsigned b0 = WS[(nt * 8 + g) * 68 + kc];
                unsigned b1 = WS[(nt * 8 + g) * 68 + kc + 4];
                mma_bf16(acc[nt], a0, a1, a2, a3, b0, b1);
            }
        }
#pragma unroll
        for (int nt = 0; nt < 8; nt++) {
            int n = nt * 8 + 2 * tig;
            float v00 = acc[nt][0] + sB3[n];
            float v01 = acc[nt][1] + sB3[n + 1];
            float v10 = acc[nt][2] + sB3[n];
            float v11 = acc[nt][3] + sB3[n + 1];
            H3[mr0 * 36 + (n >> 1)] = pack_bf16(fmaxf(v00, 0.f), fmaxf(v01, 0.f));
            H3[mr1 * 36 + (n >> 1)] = pack_bf16(fmaxf(v10, 0.f), fmaxf(v11, 0.f));
        }
    }
    __syncthreads();

    // ================= layer 4: 128 x 32 x 64 ================================
    {
        const unsigned* wsrc = (const unsigned*)g_w4_bf;
        for (int idx = t; idx < 32 * 32; idx += 256) {
            int r = idx >> 5, c = idx & 31;
            WS[r * 36 + c] = wsrc[r * 32 + c];
        }
        __syncthreads();

        float acc[4][4];
#pragma unroll
        for (int nt = 0; nt < 4; nt++)
#pragma unroll
            for (int q = 0; q < 4; q++) acc[nt][q] = 0.f;

#pragma unroll
        for (int ks = 0; ks < 4; ks++) {
            int kc = ks * 8 + tig;
            unsigned a0 = H3[mr0 * 36 + kc];
            unsigned a1 = H3[mr1 * 36 + kc];
            unsigned a2 = H3[mr0 * 36 + kc + 4];
            unsigned a3 = H3[mr1 * 36 + kc + 4];
#pragma unroll
            for (int nt = 0; nt < 4; nt++) {
                unsigned b0 = WS[(nt * 8 + g) * 36 + kc];
                unsigned b1 = WS[(nt * 8 + g) * 36 + kc + 4];
                mma_bf16(acc[nt], a0, a1, a2, a3, b0, b1);
            }
        }
#pragma unroll
        for (int nt = 0; nt < 4; nt++) {
            int n = nt * 8 + 2 * tig;
            float v00 = acc[nt][0] + sB4[n];
            float v01 = acc[nt][1] + sB4[n + 1];
            float v10 = acc[nt][2] + sB4[n];
            float v11 = acc[nt][3] + sB4[n + 1];
            H4[mr0 * 20 + (n >> 1)] = pack_bf16(fmaxf(v00, 0.f), fmaxf(v01, 0.f));
            H4[mr1 * 20 + (n >> 1)] = pack_bf16(fmaxf(v10, 0.f), fmaxf(v11, 0.f));
        }
    }
    __syncthreads();

    // ================= layer 5: 32 -> 1, diagonal mask, write ================
    if (t < 128) {
        float s = b5[0];
#pragma unroll
        for (int c = 0; c < 16; c++) {
            float2 h = unpack_bf16(H4[t * 20 + c]);
            s += h.x * sW5[2 * c] + h.y * sW5[2 * c + 1];
        }
        int j = j0 + t;
        out[i * 768 + j] = (j == i) ? -1000000000.0f : s;
    }
}

// ---------------- host launch ----------------------------------------------
extern "C" void kernel_launch(void* const* d_in, const int* in_sizes, int n_in,
                              void* d_out, int out_size)
{
    (void)in_sizes; (void)n_in; (void)out_size;
    const float* features = (const float*)d_in[0];
    const float* boxes    = (const float*)d_in[1];
    const float* in_w     = (const float*)d_in[2];
    const float* in_b     = (const float*)d_in[3];
    const float* out_w    = (const float*)d_in[4];
    const float* out_b    = (const float*)d_in[5];
    const float* w1       = (const float*)d_in[6];
    const float* b1       = (const float*)d_in[7];
    const float* lng      = (const float*)d_in[8];
    const float* lnb      = (const float*)d_in[9];
    const float* w2       = (const float*)d_in[10];
    const float* b2       = (const float*)d_in[11];
    const float* w3       = (const float*)d_in[12];
    const float* b3       = (const float*)d_in[13];
    const float* w4       = (const float*)d_in[14];
    const float* b4       = (const float*)d_in[15];
    const float* w5       = (const float*)d_in[16];
    const float* b5       = (const float*)d_in[17];
    float* out = (float*)d_out;

    float *qkv, *scores, *o, *att, *Apb, *Bpb;
    cudaGetSymbolAddress((void**)&qkv,    g_qkv);
    cudaGetSymbolAddress((void**)&scores, g_scores);
    cudaGetSymbolAddress((void**)&o,      g_o);
    cudaGetSymbolAddress((void**)&att,    g_att);
    cudaGetSymbolAddress((void**)&Apb,    g_Ap);
    cudaGetSymbolAddress((void**)&Bpb,    g_Bp);

    // weight -> bf16 conversion (independent of attention chain)
    convert_weights<<<256, 256>>>(w1, w2, w3, w4);

    // qkv = features @ in_proj_w^T + in_proj_b
    sgemm_strided<<<dim3(12, 12), 256>>>(features, 256, 1, 0,
                                         in_w, 256, 1, 0,
                                         in_b, qkv, 768, 0,
                                         768, 768, 256, 1.f);
    // scores[h] = q_h @ k_h^T / sqrt(32)
    sgemm_strided<<<dim3(12, 12, 8), 256>>>(qkv, 768, 1, 32,
                                            qkv + 256, 768, 1, 32,
                                            nullptr, scores, 768, 768L * 768,
                                            768, 768, 32, 0.17677669529663687f);
    softmax_rows<<<NHEAD * NTOK, 256>>>(scores, 768);
    // o[:, h*32+d] = attn_h @ v_h
    sgemm_strided<<<dim3(1, 12, 8), 256>>>(scores, 768, 1, 768L * 768,
                                           qkv + 512, 1, 768, 32,
                                           nullptr, o, 256, 32,
                                           768, 32, 768, 1.f);
    // att = o @ out_proj_w^T + out_proj_b
    sgemm_strided<<<dim3(4, 12), 256>>>(o, 256, 1, 0,
                                        out_w, 256, 1, 0,
                                        out_b, att, 256, 0,
                                        768, 256, 256, 1.f);
    // Ap = att @ w1[:,0:256]^T + b1 ;  Bp = att @ w1[:,256:512]^T
    sgemm_strided<<<dim3(4, 12), 256>>>(att, 256, 1, 0,
                                        w1, 771, 1, 0,
                                        b1, Apb, 256, 0,
                                        768, 256, 256, 1.f);
    sgemm_strided<<<dim3(4, 12), 256>>>(att, 256, 1, 0,
                                        w1 + 256, 771, 1, 0,
                                        nullptr, Bpb, 256, 0,
                                        768, 256, 256, 1.f);

    cudaFuncSetAttribute(fused_pairs_mma,
                         cudaFuncAttributeMaxDynamicSharedMemorySize, SMEM_BYTES);
    fused_pairs_mma<<<dim3(6, 768), 256, SMEM_BYTES>>>(
        att, boxes, w1, Apb, Bpb, lng, lnb,
        b2, b3, b4, w5, b5, out);
}

// round 5
// speedup vs baseline: 4.5387x; 1.6220x over previous
#include <cuda_runtime.h>
#include <cuda_bf16.h>
#include <cstdint>
#include <math.h>

#define NTOK 768
#define DMODEL 256
#define NHEAD 8

// ---------------- scratch (device globals; no allocations allowed) ----------
__device__ float g_qkv[NTOK * 3 * DMODEL];
__device__ float g_scores[NHEAD * NTOK * NTOK];
__device__ float g_o[NTOK * DMODEL];
__device__ float g_att[NTOK * DMODEL];
__device__ float g_Ap[NTOK * DMODEL];
__device__ float g_Bp[NTOK * DMODEL];
__device__ __nv_bfloat16 g_w1c_bf[256 * 256];
__device__ __nv_bfloat16 g_w2_bf[128 * 256];
__device__ __nv_bfloat16 g_w3_bf[64 * 128];
__device__ __nv_bfloat16 g_w4_bf[32 * 64];
__device__ __nv_bfloat16 g_att_bf[NTOK * DMODEL];
__device__ __nv_bfloat16 g_Bp_bf[NTOK * DMODEL];

// ---------------- generic strided SGEMM (prologue) ---------------------------
__global__ void sgemm_strided(const float* __restrict__ A, int asr, int asc, long aB,
                              const float* __restrict__ B, int bsr, int bsc, long bB,
                              const float* __restrict__ bias,
                              float* __restrict__ C, int csr, long cB,
                              int M, int Nc, int K, float alpha)
{
    A += (long)blockIdx.z * aB;
    B += (long)blockIdx.z * bB;
    C += (long)blockIdx.z * cB;

    __shared__ float As[16][65];
    __shared__ float Bs[16][65];

    const int m0 = blockIdx.y * 64;
    const int n0 = blockIdx.x * 64;
    const int tid = threadIdx.x;
    const int tx = tid & 15;
    const int ty = tid >> 4;

    float acc[4][4];
#pragma unroll
    for (int r = 0; r < 4; r++)
#pragma unroll
        for (int c = 0; c < 4; c++) acc[r][c] = 0.f;

    for (int kk = 0; kk < K; kk += 16) {
#pragma unroll
        for (int p = 0; p < 4; p++) {
            int idx = tid + p * 256;
            int mm = idx >> 4;
            int k  = idx & 15;
            float va = 0.f, vb = 0.f;
            if (kk + k < K) {
                if (m0 + mm < M)  va = A[(long)(m0 + mm) * asr + (long)(kk + k) * asc];
                if (n0 + mm < Nc) vb = B[(long)(n0 + mm) * bsr + (long)(kk + k) * bsc];
            }
            As[k][mm] = va;
            Bs[k][mm] = vb;
        }
        __syncthreads();
#pragma unroll
        for (int k = 0; k < 16; k++) {
            float a[4], b[4];
#pragma unroll
            for (int r = 0; r < 4; r++) a[r] = As[k][ty * 4 + r];
#pragma unroll
            for (int c = 0; c < 4; c++) b[c] = Bs[k][tx * 4 + c];
#pragma unroll
            for (int r = 0; r < 4; r++)
#pragma unroll
                for (int c = 0; c < 4; c++) acc[r][c] += a[r] * b[c];
        }
        __syncthreads();
    }

#pragma unroll
    for (int r = 0; r < 4; r++) {
        int m = m0 + ty * 4 + r;
        if (m >= M) continue;
#pragma unroll
        for (int c = 0; c < 4; c++) {
            int n = n0 + tx * 4 + c;
            if (n >= Nc) continue;
            float v = alpha * acc[r][c];
            if (bias) v += bias[n];
            C[(long)m * csr + n] = v;
        }
    }
}

// ---------------- rowwise softmax (in place) ---------------------------------
__global__ void softmax_rows(float* __restrict__ S, int cols)
{
    long r = blockIdx.x;
    float* row = S + r * (long)cols;
    int t = threadIdx.x;
    __shared__ float red[32];

    float mx = -3.4e38f;
    for (int c = t; c < cols; c += 256) mx = fmaxf(mx, row[c]);
#pragma unroll
    for (int o = 16; o > 0; o >>= 1) mx = fmaxf(mx, __shfl_xor_sync(0xffffffffu, mx, o));
    if ((t & 31) == 0) red[t >> 5] = mx;
    __syncthreads();
    float m2 = red[0];
#pragma unroll
    for (int w = 1; w < 8; w++) m2 = fmaxf(m2, red[w]);
    __syncthreads();

    float s = 0.f;
    for (int c = t; c < cols; c += 256) {
        float e = __expf(row[c] - m2);
        row[c] = e;
        s += e;
    }
#pragma unroll
    for (int o = 16; o > 0; o >>= 1) s += __shfl_xor_sync(0xffffffffu, s, o);
    if ((t & 31) == 0) red[t >> 5] = s;
    __syncthreads();
    float tot = 0.f;
#pragma unroll
    for (int w = 0; w < 8; w++) tot += red[w];
    float inv = 1.f / tot;
    for (int c = t; c < cols; c += 256) row[c] *= inv;
}

// ---------------- conversions ------------------------------------------------
__global__ void convert_weights(const float* __restrict__ w1,
                                const float* __restrict__ w2,
                                const float* __restrict__ w3,
                                const float* __restrict__ w4)
{
    int t = blockIdx.x * 256 + threadIdx.x;
    if (t < 65536) {
        int n = t >> 8, d = t & 255;
        g_w1c_bf[t] = __float2bfloat16_rn(w1[n * 771 + 512 + d]);
    }
    if (t < 32768) g_w2_bf[t] = __float2bfloat16_rn(w2[t]);
    if (t < 8192)  g_w3_bf[t] = __float2bfloat16_rn(w3[t]);
    if (t < 2048)  g_w4_bf[t] = __float2bfloat16_rn(w4[t]);
}
__global__ void convert_acts(const float* __restrict__ att,
                             const float* __restrict__ Bp)
{
    int t = blockIdx.x * 256 + threadIdx.x;
    if (t < NTOK * DMODEL) {
        g_att_bf[t] = __float2bfloat16_rn(att[t]);
        g_Bp_bf[t]  = __float2bfloat16_rn(Bp[t]);
    }
}

// ---------------- mma.sync helpers ------------------------------------------
__device__ __forceinline__ void mma_bf16(float* c, unsigned a0, unsigned a1,
                                         unsigned a2, unsigned a3,
                                         unsigned b0, unsigned b1)
{
    asm volatile(
        "mma.sync.aligned.m16n8k16.row.col.f32.bf16.bf16.f32 "
        "{%0,%1,%2,%3}, {%4,%5,%6,%7}, {%8,%9}, {%0,%1,%2,%3};"
        : "+f"(c[0]), "+f"(c[1]), "+f"(c[2]), "+f"(c[3])
        : "r"(a0), "r"(a1), "r"(a2), "r"(a3), "r"(b0), "r"(b1));
}
__device__ __forceinline__ unsigned pack_bf16(float a, float b)
{
    __nv_bfloat162 h;
    h.x = __float2bfloat16_rn(a);
    h.y = __float2bfloat16_rn(b);
    return *reinterpret_cast<unsigned*>(&h);
}
__device__ __forceinline__ float2 unpack_bf16(unsigned u)
{
    __nv_bfloat162 h = *reinterpret_cast<__nv_bfloat162*>(&u);
    return make_float2(__bfloat162float(h.x), __bfloat162float(h.y));
}

// ---------------- fused all-pairs MLP: register-resident mma.sync ------------
// Block = (i, 128 j's), 256 threads = 8 warps; warp w owns pair rows
// [w*16, w*16+16). Activations stay in registers through all layers (the
// m16n8k16 C fragment IS the next layer's A fragment). Only weights come
// from SMEM (staged once; pitches 132/68/36 -> bank = 4g+tig, conflict-free).

// SMEM u32 offsets
#define OFF_W1   0            // 256 x 132
#define OFF_W2   33792        // 128 x 132
#define OFF_W3   50688        // 64 x 68
#define OFF_W4   55040        // 32 x 36
#define OFF_PACK 56192        // float4[256] {Ap+b1, w1x, w1ya, w1ys}
#define OFF_LGB  57216        // float2[256] {ln_g, ln_b}
#define OFF_B2   57728        // float[128]
#define OFF_B3   57856        // float[64]
#define OFF_B4   57920        // float[32]
#define OFF_W5   57952        // float[32]
#define OFF_B5   57984        // float[1]
#define SMEM_U32 57988
#define SMEM_BYTES (SMEM_U32 * 4)

__global__ __launch_bounds__(256, 1) void fused_pairs_reg(
    const float* __restrict__ boxes,
    const float* __restrict__ w1,
    const float* __restrict__ Ap,
    const uint32_t* __restrict__ attbf,   // bf16x2 [768][128]
    const uint32_t* __restrict__ bpbf,    // bf16x2 [768][128]
    const uint4* __restrict__ w1v, const uint4* __restrict__ w2v,
    const uint4* __restrict__ w3v, const uint4* __restrict__ w4v,
    const float* __restrict__ lng, const float* __restrict__ lnb,
    const float* __restrict__ b2, const float* __restrict__ b3,
    const float* __restrict__ b4,
    const float* __restrict__ w5, const float* __restrict__ b5,
    float* __restrict__ out)
{
    extern __shared__ uint32_t sm[];
    uint32_t* W1s = sm + OFF_W1;
    uint32_t* W2s = sm + OFF_W2;
    uint32_t* W3s = sm + OFF_W3;
    uint32_t* W4s = sm + OFF_W4;
    float4*   sPack = (float4*)(sm + OFF_PACK);
    float2*   sLgb  = (float2*)(sm + OFF_LGB);
    float*    sB2   = (float*)(sm + OFF_B2);
    float*    sB3   = (float*)(sm + OFF_B3);
    float*    sB4   = (float*)(sm + OFF_B4);
    float*    sW5   = (float*)(sm + OFF_W5);
    float*    sB5   = (float*)(sm + OFF_B5);

    const int i  = blockIdx.y;
    const int j0 = blockIdx.x * 128;
    const int t  = threadIdx.x;
    const int w  = t >> 5;
    const int lane = t & 31;
    const int g   = lane >> 2;
    const int tig = lane & 3;

    // ---- stage weights (vectorized, once) + consts
    for (int idx = t; idx < 8192; idx += 256) {
        int r = idx >> 5, c4 = idx & 31;
        *(uint4*)&W1s[r * 132 + c4 * 4] = w1v[idx];
    }
    for (int idx = t; idx < 4096; idx += 256) {
        int r = idx >> 5, c4 = idx & 31;
        *(uint4*)&W2s[r * 132 + c4 * 4] = w2v[idx];
    }
    for (int idx = t; idx < 1024; idx += 256) {
        int r = idx >> 4, c4 = idx & 15;
        *(uint4*)&W3s[r * 68 + c4 * 4] = w3v[idx];
    }
    for (int idx = t; idx < 256; idx += 256) {
        int r = idx >> 3, c4 = idx & 7;
        *(uint4*)&W4s[r * 36 + c4 * 4] = w4v[idx];
    }
    {
        int k = t;   // 256 threads cover 256 features
        sPack[k] = make_float4(Ap[i * 256 + k], w1[k * 771 + 768],
                               w1[k * 771 + 769], w1[k * 771 + 770]);
        sLgb[k]  = make_float2(lng[k], lnb[k]);
        if (k < 128) sB2[k] = b2[k];
        if (k < 64)  sB3[k] = b3[k];
        if (k < 32)  { sB4[k] = b4[k]; sW5[k] = w5[k]; }
        if (k == 0)  sB5[0] = b5[0];
    }
    __syncthreads();   // the ONLY block-wide barrier

    const int r0 = w * 16 + g, r1 = r0 + 8;
    const int jr0 = j0 + r0, jr1 = j0 + r1;

    // spatial features for this thread's two rows
    float bxi = boxes[i * 4], byi = boxes[i * 4 + 1];
    float dy0 = byi - boxes[jr0 * 4 + 1];
    float dy1 = byi - boxes[jr1 * 4 + 1];
    float sx0 = fabsf(bxi - boxes[jr0 * 4]), sya0 = fabsf(dy0), sys0 = dy0;
    float sx1 = fabsf(bxi - boxes[jr1 * 4]), sya1 = fabsf(dy1), sys1 = dy1;

    // ---- build layer-1 A fragments in registers: P = att_j (.) att_i
    uint32_t A1[64];
#pragma unroll
    for (int q = 0; q < 16; q++) {
        int p0 = 8 * q + tig, p1 = p0 + 4;
        float2 ai0 = unpack_bf16(attbf[i * 128 + p0]);
        float2 ai1 = unpack_bf16(attbf[i * 128 + p1]);
        float2 j00 = unpack_bf16(attbf[jr0 * 128 + p0]);
        float2 j10 = unpack_bf16(attbf[jr1 * 128 + p0]);
        float2 j01 = unpack_bf16(attbf[jr0 * 128 + p1]);
        float2 j11 = unpack_bf16(attbf[jr1 * 128 + p1]);
        A1[4 * q]     = pack_bf16(j00.x * ai0.x, j00.y * ai0.y);
        A1[4 * q + 1] = pack_bf16(j10.x * ai0.x, j10.y * ai0.y);
        A1[4 * q + 2] = pack_bf16(j01.x * ai1.x, j01.y * ai1.y);
        A1[4 * q + 3] = pack_bf16(j11.x * ai1.x, j11.y * ai1.y);
    }

    // ================= layer 1: N=256, K=256 (two n-halves of 16 tiles) ======
    uint32_t H1[64];
    float sum0 = 0.f, sq0 = 0.f, sum1 = 0.f, sq1 = 0.f;
#pragma unroll
    for (int h = 0; h < 2; h++) {
        float acc[16][4];
#pragma unroll
        for (int ntl = 0; ntl < 16; ntl++)
#pragma unroll
            for (int q = 0; q < 4; q++) acc[ntl][q] = 0.f;

#pragma unroll
        for (int q = 0; q < 16; q++) {
            uint32_t a0 = A1[4 * q],     a1 = A1[4 * q + 1];
            uint32_t a2 = A1[4 * q + 2], a3 = A1[4 * q + 3];
#pragma unroll
            for (int ntl = 0; ntl < 16; ntl++) {
                int n = (h * 16 + ntl) * 8 + g;
                uint32_t b0 = W1s[n * 132 + 8 * q + tig];
                uint32_t b1 = W1s[n * 132 + 8 * q + 4 + tig];
                mma_bf16(acc[ntl], a0, a1, a2, a3, b0, b1);
            }
        }
        // epilogue: + Ap + spatial + Bp, relu, pack into next-layer A slots
#pragma unroll
        for (int ntl = 0; ntl < 16; ntl++) {
            int nt = h * 16 + ntl;
            int c0 = 8 * nt + 2 * tig;
            float4 p0 = sPack[c0], p1 = sPack[c0 + 1];
            float2 bp0 = unpack_bf16(bpbf[jr0 * 128 + 4 * nt + tig]);
            float2 bp1 = unpack_bf16(bpbf[jr1 * 128 + 4 * nt + tig]);
            float v00 = acc[ntl][0] + p0.x + sx0 * p0.y + sya0 * p0.z + sys0 * p0.w + bp0.x;
            float v01 = acc[ntl][1] + p1.x + sx0 * p1.y + sya0 * p1.z + sys0 * p1.w + bp0.y;
            float v10 = acc[ntl][2] + p0.x + sx1 * p0.y + sya1 * p0.z + sys1 * p0.w + bp1.x;
            float v11 = acc[ntl][3] + p1.x + sx1 * p1.y + sya1 * p1.z + sys1 * p1.w + bp1.y;
            v00 = fmaxf(v00, 0.f); v01 = fmaxf(v01, 0.f);
            v10 = fmaxf(v10, 0.f); v11 = fmaxf(v11, 0.f);
            sum0 += v00 + v01; sq0 += v00 * v00 + v01 * v01;
            sum1 += v10 + v11; sq1 += v10 * v10 + v11 * v11;
            int q2 = nt >> 1, off = (nt & 1) * 2;
            H1[4 * q2 + off]     = pack_bf16(v00, v01);
            H1[4 * q2 + off + 1] = pack_bf16(v10, v11);
        }
    }

    // ================= layernorm (quad-local reductions) ======================
#pragma unroll
    for (int o = 1; o <= 2; o <<= 1) {
        sum0 += __shfl_xor_sync(0xffffffffu, sum0, o);
        sq0  += __shfl_xor_sync(0xffffffffu, sq0,  o);
        sum1 += __shfl_xor_sync(0xffffffffu, sum1, o);
        sq1  += __shfl_xor_sync(0xffffffffu, sq1,  o);
    }
    float mu0 = sum0 * (1.f / 256.f);
    float rs0 = rsqrtf(sq0 * (1.f / 256.f) - mu0 * mu0 + 1e-5f);
    float mu1 = sum1 * (1.f / 256.f);
    float rs1 = rsqrtf(sq1 * (1.f / 256.f) - mu1 * mu1 + 1e-5f);
#pragma unroll
    for (int q = 0; q < 16; q++) {
#pragma unroll
        for (int e2 = 0; e2 < 2; e2++) {
            int col = 16 * q + 8 * e2 + 2 * tig;
            float2 gb0 = sLgb[col], gb1 = sLgb[col + 1];
#pragma unroll
            for (int e = 0; e < 2; e++) {
                int idx = 4 * q + 2 * e2 + e;
                float2 v = unpack_bf16(H1[idx]);
                float m = e ? mu1 : mu0, rr = e ? rs1 : rs0;
                H1[idx] = pack_bf16((v.x - m) * rr * gb0.x + gb0.y,
                                    (v.y - m) * rr * gb1.x + gb1.y);
            }
        }
    }

    // ================= layer 2: N=128, K=256 =================================
    uint32_t H2[32];
#pragma unroll
    for (int h = 0; h < 2; h++) {
        float acc[8][4];
#pragma unroll
        for (int ntl = 0; ntl < 8; ntl++)
#pragma unroll
            for (int q = 0; q < 4; q++) acc[ntl][q] = 0.f;
#pragma unroll
        for (int q = 0; q < 16; q++) {
            uint32_t a0 = H1[4 * q],     a1 = H1[4 * q + 1];
            uint32_t a2 = H1[4 * q + 2], a3 = H1[4 * q + 3];
#pragma unroll
            for (int ntl = 0; ntl < 8; ntl++) {
                int n = (h * 8 + ntl) * 8 + g;
                uint32_t b0 = W2s[n * 132 + 8 * q + tig];
                uint32_t b1 = W2s[n * 132 + 8 * q + 4 + tig];
                mma_bf16(acc[ntl], a0, a1, a2, a3, b0, b1);
            }
        }
#pragma unroll
        for (int ntl = 0; ntl < 8; ntl++) {
            int nt = h * 8 + ntl;
            int c0 = 8 * nt + 2 * tig;
            float v00 = fmaxf(acc[ntl][0] + sB2[c0], 0.f);
            float v01 = fmaxf(acc[ntl][1] + sB2[c0 + 1], 0.f);
            float v10 = fmaxf(acc[ntl][2] + sB2[c0], 0.f);
            float v11 = fmaxf(acc[ntl][3] + sB2[c0 + 1], 0.f);
            int q2 = nt >> 1, off = (nt & 1) * 2;
            H2[4 * q2 + off]     = pack_bf16(v00, v01);
            H2[4 * q2 + off + 1] = pack_bf16(v10, v11);
        }
    }

    // ================= layer 3: N=64, K=128 ==================================
    uint32_t H3[16];
    {
        float acc[8][4];
#pragma unroll
        for (int ntl = 0; ntl < 8; ntl++)
#pragma unroll
            for (int q = 0; q < 4; q++) acc[ntl][q] = 0.f;
#pragma unroll
        for (int q = 0; q < 8; q++) {
            uint32_t a0 = H2[4 * q],     a1 = H2[4 * q + 1];
            uint32_t a2 = H2[4 * q + 2], a3 = H2[4 * q + 3];
#pragma unroll
            for (int ntl = 0; ntl < 8; ntl++) {
                int n = ntl * 8 + g;
                uint32_t b0 = W3s[n * 68 + 8 * q + tig];
                uint32_t b1 = W3s[n * 68 + 8 * q + 4 + tig];
                mma_bf16(acc[ntl], a0, a1, a2, a3, b0, b1);
            }
        }
#pragma unroll
        for (int nt = 0; nt < 8; nt++) {
            int c0 = 8 * nt + 2 * tig;
            float v00 = fmaxf(acc[nt][0] + sB3[c0], 0.f);
            float v01 = fmaxf(acc[nt][1] + sB3[c0 + 1], 0.f);
            float v10 = fmaxf(acc[nt][2] + sB3[c0], 0.f);
            float v11 = fmaxf(acc[nt][3] + sB3[c0 + 1], 0.f);
            int q2 = nt >> 1, off = (nt & 1) * 2;
            H3[4 * q2 + off]     = pack_bf16(v00, v01);
            H3[4 * q2 + off + 1] = pack_bf16(v10, v11);
        }
    }

    // ================= layer 4 (N=32, K=64) + layer 5 dot ====================
    {
        float acc[4][4];
#pragma unroll
        for (int ntl = 0; ntl < 4; ntl++)
#pragma unroll
            for (int q = 0; q < 4; q++) acc[ntl][q] = 0.f;
#pragma unroll
        for (int q = 0; q < 4; q++) {
            uint32_t a0 = H3[4 * q],     a1 = H3[4 * q + 1];
            uint32_t a2 = H3[4 * q + 2], a3 = H3[4 * q + 3];
#pragma unroll
            for (int ntl = 0; ntl < 4; ntl++) {
                int n = ntl * 8 + g;
                uint32_t b0 = W4s[n * 36 + 8 * q + tig];
                uint32_t b1 = W4s[n * 36 + 8 * q + 4 + tig];
                mma_bf16(acc[ntl], a0, a1, a2, a3, b0, b1);
            }
        }
        float p0 = 0.f, p1 = 0.f;
#pragma unroll
        for (int nt = 0; nt < 4; nt++) {
            int c0 = 8 * nt + 2 * tig;
            p0 += fmaxf(acc[nt][0] + sB4[c0], 0.f) * sW5[c0]
                + fmaxf(acc[nt][1] + sB4[c0 + 1], 0.f) * sW5[c0 + 1];
            p1 += fmaxf(acc[nt][2] + sB4[c0], 0.f) * sW5[c0]
                + fmaxf(acc[nt][3] + sB4[c0 + 1], 0.f) * sW5[c0 + 1];
        }
#pragma unroll
        for (int o = 1; o <= 2; o <<= 1) {
            p0 += __shfl_xor_sync(0xffffffffu, p0, o);
            p1 += __shfl_xor_sync(0xffffffffu, p1, o);
        }
        if (tig == 0) {
            float bb = sB5[0];
            out[i * 768 + jr0] = (jr0 == i) ? -1000000000.0f : p0 + bb;
            out[i * 768 + jr1] = (jr1 == i) ? -1000000000.0f : p1 + bb;
        }
    }
}

// ---------------- host launch ------------------------------------------------
extern "C" void kernel_launch(void* const* d_in, const int* in_sizes, int n_in,
                              void* d_out, int out_size)
{
    (void)in_sizes; (void)n_in; (void)out_size;
    const float* features = (const float*)d_in[0];
    const float* boxes    = (const float*)d_in[1];
    const float* in_w     = (const float*)d_in[2];
    const float* in_b     = (const float*)d_in[3];
    const float* out_w    = (const float*)d_in[4];
    const float* out_b    = (const float*)d_in[5];
    const float* w1       = (const float*)d_in[6];
    const float* b1       = (const float*)d_in[7];
    const float* lng      = (const float*)d_in[8];
    const float* lnb      = (const float*)d_in[9];
    const float* w2       = (const float*)d_in[10];
    const float* b2       = (const float*)d_in[11];
    const float* w3       = (const float*)d_in[12];
    const float* b3       = (const float*)d_in[13];
    const float* w4       = (const float*)d_in[14];
    const float* b4       = (const float*)d_in[15];
    const float* w5       = (const float*)d_in[16];
    const float* b5       = (const float*)d_in[17];
    float* out = (float*)d_out;

    float *qkv, *scores, *o, *att, *Apb, *Bpb;
    void *attbf, *bpbf, *w1bf, *w2bf, *w3bf, *w4bf;
    cudaGetSymbolAddress((void**)&qkv,    g_qkv);
    cudaGetSymbolAddress((void**)&scores, g_scores);
    cudaGetSymbolAddress((void**)&o,      g_o);
    cudaGetSymbolAddress((void**)&att,    g_att);
    cudaGetSymbolAddress((void**)&Apb,    g_Ap);
    cudaGetSymbolAddress((void**)&Bpb,    g_Bp);
    cudaGetSymbolAddress(&attbf, g_att_bf);
    cudaGetSymbolAddress(&bpbf,  g_Bp_bf);
    cudaGetSymbolAddress(&w1bf,  g_w1c_bf);
    cudaGetSymbolAddress(&w2bf,  g_w2_bf);
    cudaGetSymbolAddress(&w3bf,  g_w3_bf);
    cudaGetSymbolAddress(&w4bf,  g_w4_bf);

    convert_weights<<<256, 256>>>(w1, w2, w3, w4);

    // qkv = features @ in_proj_w^T + in_proj_b
    sgemm_strided<<<dim3(12, 12), 256>>>(features, 256, 1, 0,
                                         in_w, 256, 1, 0,
                                         in_b, qkv, 768, 0,
                                         768, 768, 256, 1.f);
    // scores[h] = q_h @ k_h^T / sqrt(32)
    sgemm_strided<<<dim3(12, 12, 8), 256>>>(qkv, 768, 1, 32,
                                            qkv + 256, 768, 1, 32,
                                            nullptr, scores, 768, 768L * 768,
                                            768, 768, 32, 0.17677669529663687f);
    softmax_rows<<<NHEAD * NTOK, 256>>>(scores, 768);
    // o[:, h*32+d] = attn_h @ v_h
    sgemm_strided<<<dim3(1, 12, 8), 256>>>(scores, 768, 1, 768L * 768,
                                           qkv + 512, 1, 768, 32,
                                           nullptr, o, 256, 32,
                                           768, 32, 768, 1.f);
    // att = o @ out_proj_w^T + out_proj_b
    sgemm_strided<<<dim3(4, 12), 256>>>(o, 256, 1, 0,
                                        out_w, 256, 1, 0,
                                        out_b, att, 256, 0,
                                        768, 256, 256, 1.f);
    // Ap = att @ w1[:,0:256]^T + b1 ;  Bp = att @ w1[:,256:512]^T
    sgemm_strided<<<dim3(4, 12), 256>>>(att, 256, 1, 0,
                                        w1, 771, 1, 0,
                                        b1, Apb, 256, 0,
                                        768, 256, 256, 1.f);
    sgemm_strided<<<dim3(4, 12), 256>>>(att, 256, 1, 0,
                                        w1 + 256, 771, 1, 0,
                                        nullptr, Bpb, 256, 0,
                                        768, 256, 256, 1.f);
    convert_acts<<<768, 256>>>(att, Bpb);

    cudaFuncSetAttribute(fused_pairs_reg,
                         cudaFuncAttributeMaxDynamicSharedMemorySize, SMEM_BYTES);
    fused_pairs_reg<<<dim3(6, 768), 256, SMEM_BYTES>>>(
        boxes, w1, Apb,
        (const uint32_t*)attbf, (const uint32_t*)bpbf,
        (const uint4*)w1bf, (const uint4*)w2bf,
        (const uint4*)w3bf, (const uint4*)w4bf,
        lng, lnb, b2, b3, b4, w5, b5, out);
}

// round 6
// speedup vs baseline: 5.6927x; 1.2542x over previous
#include <cuda_runtime.h>
#include <cuda_bf16.h>
#include <cstdint>
#include <math.h>

#define NTOK 768
#define DMODEL 256
#define NHEAD 8

// ---------------- scratch (device globals; no allocations allowed) ----------
__device__ __nv_bfloat16 g_feat_bf[NTOK * DMODEL];
__device__ __nv_bfloat16 g_inw_bf[768 * 256];
__device__ __nv_bfloat16 g_outw_bf[256 * 256];
__device__ __nv_bfloat16 g_w1a_bf[256 * 256];
__device__ __nv_bfloat16 g_w1b_bf[256 * 256];
__device__ __nv_bfloat16 g_w1c_bf[256 * 256];
__device__ __nv_bfloat16 g_w2_bf[128 * 256];
__device__ __nv_bfloat16 g_w3_bf[64 * 128];
__device__ __nv_bfloat16 g_w4_bf[32 * 64];
__device__ __nv_bfloat16 g_qkv_bf[NTOK * 768];     // qkv in bf16
__device__ __nv_bfloat16 g_vT_bf[NHEAD * 32 * NTOK]; // V transposed per head
__device__ __nv_bfloat16 g_o_bf[NTOK * DMODEL];    // attention out (bf16)
__device__ __nv_bfloat16 g_att_bf[NTOK * DMODEL];
__device__ __nv_bfloat16 g_Bp_bf[NTOK * DMODEL];
__device__ float g_Ap[NTOK * DMODEL];

// ---------------- helpers ----------------------------------------------------
__device__ __forceinline__ void mma_bf16(float* c, unsigned a0, unsigned a1,
                                         unsigned a2, unsigned a3,
                                         unsigned b0, unsigned b1)
{
    asm volatile(
        "mma.sync.aligned.m16n8k16.row.col.f32.bf16.bf16.f32 "
        "{%0,%1,%2,%3}, {%4,%5,%6,%7}, {%8,%9}, {%0,%1,%2,%3};"
        : "+f"(c[0]), "+f"(c[1]), "+f"(c[2]), "+f"(c[3])
        : "r"(a0), "r"(a1), "r"(a2), "r"(a3), "r"(b0), "r"(b1));
}
__device__ __forceinline__ unsigned pack_bf16(float a, float b)
{
    __nv_bfloat162 h;
    h.x = __float2bfloat16_rn(a);
    h.y = __float2bfloat16_rn(b);
    return *reinterpret_cast<unsigned*>(&h);
}
__device__ __forceinline__ float2 unpack_bf16(unsigned u)
{
    __nv_bfloat162 h = *reinterpret_cast<__nv_bfloat162*>(&u);
    return make_float2(__bfloat162float(h.x), __bfloat162float(h.y));
}
__device__ __forceinline__ float fexp2(float x)
{
    float y;
    asm("ex2.approx.ftz.f32 %0, %1;" : "=f"(y) : "f"(x));
    return y;
}

// ---------------- conversions -------------------------------------------------
__global__ void convert_pre(const float* __restrict__ features,
                            const float* __restrict__ in_w,
                            const float* __restrict__ out_w,
                            const float* __restrict__ w1,
                            const float* __restrict__ w2,
                            const float* __restrict__ w3,
                            const float* __restrict__ w4)
{
    int t = blockIdx.x * 256 + threadIdx.x;
    if (t < 196608) {
        g_feat_bf[t] = __float2bfloat16_rn(features[t]);
        g_inw_bf[t]  = __float2bfloat16_rn(in_w[t]);
    }
    if (t < 65536) {
        int n = t >> 8, d = t & 255;
        g_outw_bf[t] = __float2bfloat16_rn(out_w[t]);
        g_w1a_bf[t]  = __float2bfloat16_rn(w1[n * 771 + d]);
        g_w1b_bf[t]  = __float2bfloat16_rn(w1[n * 771 + 256 + d]);
        g_w1c_bf[t]  = __float2bfloat16_rn(w1[n * 771 + 512 + d]);
    }
    if (t < 32768) g_w2_bf[t] = __float2bfloat16_rn(w2[t]);
    if (t < 8192)  g_w3_bf[t] = __float2bfloat16_rn(w3[t]);
    if (t < 2048)  g_w4_bf[t] = __float2bfloat16_rn(w4[t]);
}

// vT[h*32+d][m] = qkv_bf[m][512 + h*32 + d]
__global__ void build_vT()
{
    int row = blockIdx.x;          // 0..255
    for (int m = threadIdx.x; m < NTOK; m += 256)
        g_vT_bf[row * NTOK + m] = g_qkv_bf[m * 768 + 512 + row];
}

// ---------------- bf16 tensor-core GEMM: C = A(MxK) @ B(NxK)^T + bias --------
// K fixed = 256. 128x128 tile per block, 256 threads. Same fragment scheme
// as the fused kernel (proven in R5). Writes fp32 Cf and/or bf16x2 Cb.
#define GEMM_SMEM_U32 33792
#define GEMM_SMEM_BYTES (GEMM_SMEM_U32 * 4)

__global__ __launch_bounds__(256, 1) void gemm_bf256(
    const uint4* __restrict__ A4,   // [M][32] uint4
    const uint4* __restrict__ B4,   // [N][32] uint4
    const float* __restrict__ bias, // [N] or null
    float* __restrict__ Cf,         // [M][N] or null
    uint32_t* __restrict__ Cb,      // [M][N/2] or null
    int N)
{
    extern __shared__ uint32_t sg[];
    uint32_t* As = sg;              // 128 x 132
    uint32_t* Bs = sg + 16896;      // 128 x 132

    const int m0 = blockIdx.y * 128;
    const int n0 = blockIdx.x * 128;
    const int t  = threadIdx.x;
    const int w  = t >> 5;
    const int lane = t & 31;
    const int g   = lane >> 2;
    const int tig = lane & 3;
    const int r0i = w * 16 + g, r1i = r0i + 8;

    for (int idx = t; idx < 4096; idx += 256) {
        int r = idx >> 5, c4 = idx & 31;
        *(uint4*)&As[r * 132 + c4 * 4] = A4[(m0 + r) * 32 + c4];
        *(uint4*)&Bs[r * 132 + c4 * 4] = B4[(n0 + r) * 32 + c4];
    }
    __syncthreads();

    float acc[16][4];
#pragma unroll
    for (int nt = 0; nt < 16; nt++)
#pragma unroll
        for (int q = 0; q < 4; q++) acc[nt][q] = 0.f;

#pragma unroll
    for (int q = 0; q < 16; q++) {
        uint32_t a0 = As[r0i * 132 + 8 * q + tig];
        uint32_t a1 = As[r1i * 132 + 8 * q + tig];
        uint32_t a2 = As[r0i * 132 + 8 * q + 4 + tig];
        uint32_t a3 = As[r1i * 132 + 8 * q + 4 + tig];
#pragma unroll
        for (int nt = 0; nt < 16; nt++) {
            int n = 8 * nt + g;
            uint32_t b0 = Bs[n * 132 + 8 * q + tig];
            uint32_t b1 = Bs[n * 132 + 8 * q + 4 + tig];
            mma_bf16(acc[nt], a0, a1, a2, a3, b0, b1);
        }
    }

    const int gm0 = m0 + r0i, gm1 = m0 + r1i;
#pragma unroll
    for (int nt = 0; nt < 16; nt++) {
        int gn = n0 + 8 * nt + 2 * tig;
        float bi0 = bias ? bias[gn] : 0.f;
        float bi1 = bias ? bias[gn + 1] : 0.f;
        float v00 = acc[nt][0] + bi0, v01 = acc[nt][1] + bi1;
        float v10 = acc[nt][2] + bi0, v11 = acc[nt][3] + bi1;
        if (Cf) {
            *(float2*)&Cf[(size_t)gm0 * N + gn] = make_float2(v00, v01);
            *(float2*)&Cf[(size_t)gm1 * N + gn] = make_float2(v10, v11);
        }
        if (Cb) {
            Cb[gm0 * (N >> 1) + (gn >> 1)] = pack_bf16(v00, v01);
            Cb[gm1 * (N >> 1) + (gn >> 1)] = pack_bf16(v10, v11);
        }
    }
}

// ---------------- flash attention: scores+softmax+attn@V ---------------------
// Grid (6 q-tiles, 8 heads), 256 threads. Warp owns 16 q-rows. Online softmax
// in base-2 domain; S C-fragments repack directly into P A-fragments.
__global__ __launch_bounds__(256, 1) void attn_flash(float* /*unused*/)
{
    __shared__ uint32_t Ks[128 * 20];   // k tile: 128 rows x 16 u32
    __shared__ uint32_t VTs[32 * 68];   // vT tile: 32 rows x 64 u32

    const int q0 = blockIdx.x * 128;
    const int h  = blockIdx.y;
    const int t  = threadIdx.x;
    const int w  = t >> 5;
    const int lane = t & 31;
    const int g   = lane >> 2;
    const int tig = lane & 3;
    const int r0i = w * 16 + g, r1i = r0i + 8;

    const uint32_t* qkvU = (const uint32_t*)g_qkv_bf;   // row = 384 u32
    const uint32_t* vtU  = (const uint32_t*)g_vT_bf;    // row = 384 u32

    const float CS = 1.4426950408889634f * 0.17677669529663687f;

    // q fragments (K=32 -> 2 k-groups)
    uint32_t qf[8];
#pragma unroll
    for (int qq = 0; qq < 2; qq++) {
        qf[4 * qq]     = qkvU[(q0 + r0i) * 384 + h * 16 + 8 * qq + tig];
        qf[4 * qq + 1] = qkvU[(q0 + r1i) * 384 + h * 16 + 8 * qq + tig];
        qf[4 * qq + 2] = qkvU[(q0 + r0i) * 384 + h * 16 + 8 * qq + 4 + tig];
        qf[4 * qq + 3] = qkvU[(q0 + r1i) * 384 + h * 16 + 8 * qq + 4 + tig];
    }

    float acc_o[4][4];
#pragma unroll
    for (int nt = 0; nt < 4; nt++)
#pragma unroll
        for (int e = 0; e < 4; e++) acc_o[nt][e] = 0.f;
    float m0s = -1e30f, m1s = -1e30f, l0p = 0.f, l1p = 0.f;

    for (int kt = 0; kt < 6; kt++) {
        __syncthreads();
        for (int idx = t; idx < 2048; idx += 256) {
            int r = idx >> 4, c = idx & 15;
            Ks[r * 20 + c] = qkvU[(kt * 128 + r) * 384 + 128 + h * 16 + c];
        }
        for (int idx = t; idx < 2048; idx += 256) {
            int d = idx >> 6, c = idx & 63;
            VTs[d * 68 + c] = vtU[(h * 32 + d) * 384 + kt * 64 + c];
        }
        __syncthreads();

        // S = q @ k^T  (M=16, N=128, K=32)
        float accs[16][4];
#pragma unroll
        for (int nt = 0; nt < 16; nt++)
#pragma unroll
            for (int e = 0; e < 4; e++) accs[nt][e] = 0.f;
#pragma unroll
        for (int qq = 0; qq < 2; qq++) {
            uint32_t a0 = qf[4 * qq], a1 = qf[4 * qq + 1];
            uint32_t a2 = qf[4 * qq + 2], a3 = qf[4 * qq + 3];
#pragma unroll
            for (int nt = 0; nt < 16; nt++) {
                int n = 8 * nt + g;
                uint32_t b0 = Ks[n * 20 + 8 * qq + tig];
                uint32_t b1 = Ks[n * 20 + 8 * qq + 4 + tig];
                mma_bf16(accs[nt], a0, a1, a2, a3, b0, b1);
            }
        }
        // scale into base-2 domain, row max
        float lm0 = -1e30f, lm1 = -1e30f;
#pragma unroll
        for (int nt = 0; nt < 16; nt++) {
            accs[nt][0] *= CS; accs[nt][1] *= CS;
            accs[nt][2] *= CS; accs[nt][3] *= CS;
            lm0 = fmaxf(lm0, fmaxf(accs[nt][0], accs[nt][1]));
            lm1 = fmaxf(lm1, fmaxf(accs[nt][2], accs[nt][3]));
        }
#pragma unroll
        for (int o = 1; o <= 2; o <<= 1) {
            lm0 = fmaxf(lm0, __shfl_xor_sync(0xffffffffu, lm0, o));
            lm1 = fmaxf(lm1, __shfl_xor_sync(0xffffffffu, lm1, o));
        }
        float mn0 = fmaxf(m0s, lm0), mn1 = fmaxf(m1s, lm1);
        float al0 = fexp2(m0s - mn0), al1 = fexp2(m1s - mn1);
        m0s = mn0; m1s = mn1;

        float ps0 = 0.f, ps1 = 0.f;
        uint32_t Pf[32];
#pragma unroll
        for (int nt = 0; nt < 16; nt++) {
            float p00 = fexp2(accs[nt][0] - mn0);
            float p01 = fexp2(accs[nt][1] - mn0);
            float p10 = fexp2(accs[nt][2] - mn1);
            float p11 = fexp2(accs[nt][3] - mn1);
            ps0 += p00 + p01; ps1 += p10 + p11;
            int q2 = nt >> 1, off = (nt & 1) * 2;
            Pf[4 * q2 + off]     = pack_bf16(p00, p01);
            Pf[4 * q2 + off + 1] = pack_bf16(p10, p11);
        }
        l0p = l0p * al0 + ps0;
        l1p = l1p * al1 + ps1;
#pragma unroll
        for (int nt = 0; nt < 4; nt++) {
            acc_o[nt][0] *= al0; acc_o[nt][1] *= al0;
            acc_o[nt][2] *= al1; acc_o[nt][3] *= al1;
        }
        // o += P @ V  (M=16, N=32, K=128)
#pragma unroll
        for (int q = 0; q < 8; q++) {
            uint32_t a0 = Pf[4 * q], a1 = Pf[4 * q + 1];
            uint32_t a2 = Pf[4 * q + 2], a3 = Pf[4 * q + 3];
#pragma unroll
            for (int nt = 0; nt < 4; nt++) {
                int n = 8 * nt + g;
                uint32_t b0 = VTs[n * 68 + 8 * q + tig];
                uint32_t b1 = VTs[n * 68 + 8 * q + 4 + tig];
                mma_bf16(acc_o[nt], a0, a1, a2, a3, b0, b1);
            }
        }
    }

    // finalize: l = quad-sum, divide, write bf16 o
#pragma unroll
    for (int o = 1; o <= 2; o <<= 1) {
        l0p += __shfl_xor_sync(0xffffffffu, l0p, o);
        l1p += __shfl_xor_sync(0xffffffffu, l1p, o);
    }
    float inv0 = 1.f / l0p, inv1 = 1.f / l1p;
    uint32_t* oU = (uint32_t*)g_o_bf;   // row = 128 u32
#pragma unroll
    for (int nt = 0; nt < 4; nt++) {
        oU[(q0 + r0i) * 128 + h * 16 + 4 * nt + tig] =
            pack_bf16(acc_o[nt][0] * inv0, acc_o[nt][1] * inv0);
        oU[(q0 + r1i) * 128 + h * 16 + 4 * nt + tig] =
            pack_bf16(acc_o[nt][2] * inv1, acc_o[nt][3] * inv1);
    }
}

// ---------------- fused all-pairs MLP (unchanged from R5) --------------------
#define OFF_W1   0
#define OFF_W2   33792
#define OFF_W3   50688
#define OFF_W4   55040
#define OFF_PACK 56192
#define OFF_LGB  57216
#define OFF_B2   57728
#define OFF_B3   57856
#define OFF_B4   57920
#define OFF_W5   57952
#define OFF_B5   57984
#define SMEM_U32 57988
#define SMEM_BYTES (SMEM_U32 * 4)

__global__ __launch_bounds__(256, 1) void fused_pairs_reg(
    const float* __restrict__ boxes,
    const float* __restrict__ w1,
    const float* __restrict__ Ap,
    const uint32_t* __restrict__ attbf,
    const uint32_t* __restrict__ bpbf,
    const uint4* __restrict__ w1v, const uint4* __restrict__ w2v,
    const uint4* __restrict__ w3v, const uint4* __restrict__ w4v,
    const float* __restrict__ lng, const float* __restrict__ lnb,
    const float* __restrict__ b2, const float* __restrict__ b3,
    const float* __restrict__ b4,
    const float* __restrict__ w5, const float* __restrict__ b5,
    float* __restrict__ out)
{
    extern __shared__ uint32_t sm[];
    uint32_t* W1s = sm + OFF_W1;
    uint32_t* W2s = sm + OFF_W2;
    uint32_t* W3s = sm + OFF_W3;
    uint32_t* W4s = sm + OFF_W4;
    float4*   sPack = (float4*)(sm + OFF_PACK);
    float2*   sLgb  = (float2*)(sm + OFF_LGB);
    float*    sB2   = (float*)(sm + OFF_B2);
    float*    sB3   = (float*)(sm + OFF_B3);
    float*    sB4   = (float*)(sm + OFF_B4);
    float*    sW5   = (float*)(sm + OFF_W5);
    float*    sB5   = (float*)(sm + OFF_B5);

    const int i  = blockIdx.y;
    const int j0 = blockIdx.x * 128;
    const int t  = threadIdx.x;
    const int w  = t >> 5;
    const int lane = t & 31;
    const int g   = lane >> 2;
    const int tig = lane & 3;

    for (int idx = t; idx < 8192; idx += 256) {
        int r = idx >> 5, c4 = idx & 31;
        *(uint4*)&W1s[r * 132 + c4 * 4] = w1v[idx];
    }
    for (int idx = t; idx < 4096; idx += 256) {
        int r = idx >> 5, c4 = idx & 31;
        *(uint4*)&W2s[r * 132 + c4 * 4] = w2v[idx];
    }
    for (int idx = t; idx < 1024; idx += 256) {
        int r = idx >> 4, c4 = idx & 15;
        *(uint4*)&W3s[r * 68 + c4 * 4] = w3v[idx];
    }
    for (int idx = t; idx < 256; idx += 256) {
        int r = idx >> 3, c4 = idx & 7;
        *(uint4*)&W4s[r * 36 + c4 * 4] = w4v[idx];
    }
    {
        int k = t;
        sPack[k] = make_float4(Ap[i * 256 + k], w1[k * 771 + 768],
                               w1[k * 771 + 769], w1[k * 771 + 770]);
        sLgb[k]  = make_float2(lng[k], lnb[k]);
        if (k < 128) sB2[k] = b2[k];
        if (k < 64)  sB3[k] = b3[k];
        if (k < 32)  { sB4[k] = b4[k]; sW5[k] = w5[k]; }
        if (k == 0)  sB5[0] = b5[0];
    }
    __syncthreads();

    const int r0 = w * 16 + g, r1 = r0 + 8;
    const int jr0 = j0 + r0, jr1 = j0 + r1;

    float bxi = boxes[i * 4], byi = boxes[i * 4 + 1];
    float dy0 = byi - boxes[jr0 * 4 + 1];
    float dy1 = byi - boxes[jr1 * 4 + 1];
    float sx0 = fabsf(bxi - boxes[jr0 * 4]), sya0 = fabsf(dy0), sys0 = dy0;
    float sx1 = fabsf(bxi - boxes[jr1 * 4]), sya1 = fabsf(dy1), sys1 = dy1;

    uint32_t A1[64];
#pragma unroll
    for (int q = 0; q < 16; q++) {
        int p0 = 8 * q + tig, p1 = p0 + 4;
        float2 ai0 = unpack_bf16(attbf[i * 128 + p0]);
        float2 ai1 = unpack_bf16(attbf[i * 128 + p1]);
        float2 j00 = unpack_bf16(attbf[jr0 * 128 + p0]);
        float2 j10 = unpack_bf16(attbf[jr1 * 128 + p0]);
        float2 j01 = unpack_bf16(attbf[jr0 * 128 + p1]);
        float2 j11 = unpack_bf16(attbf[jr1 * 128 + p1]);
        A1[4 * q]     = pack_bf16(j00.x * ai0.x, j00.y * ai0.y);
        A1[4 * q + 1] = pack_bf16(j10.x * ai0.x, j10.y * ai0.y);
        A1[4 * q + 2] = pack_bf16(j01.x * ai1.x, j01.y * ai1.y);
        A1[4 * q + 3] = pack_bf16(j11.x * ai1.x, j11.y * ai1.y);
    }

    uint32_t H1[64];
    float sum0 = 0.f, sq0 = 0.f, sum1 = 0.f, sq1 = 0.f;
#pragma unroll
    for (int h = 0; h < 2; h++) {
        float acc[16][4];
#pragma unroll
        for (int ntl = 0; ntl < 16; ntl++)
#pragma unroll
            for (int q = 0; q < 4; q++) acc[ntl][q] = 0.f;

#pragma unroll
        for (int q = 0; q < 16; q++) {
            uint32_t a0 = A1[4 * q],     a1 = A1[4 * q + 1];
            uint32_t a2 = A1[4 * q + 2], a3 = A1[4 * q + 3];
#pragma unroll
            for (int ntl = 0; ntl < 16; ntl++) {
                int n = (h * 16 + ntl) * 8 + g;
                uint32_t b0 = W1s[n * 132 + 8 * q + tig];
                uint32_t b1 = W1s[n * 132 + 8 * q + 4 + tig];
                mma_bf16(acc[ntl], a0, a1, a2, a3, b0, b1);
            }
        }
#pragma unroll
        for (int ntl = 0; ntl < 16; ntl++) {
            int nt = h * 16 + ntl;
            int c0 = 8 * nt + 2 * tig;
            float4 p0 = sPack[c0], p1 = sPack[c0 + 1];
            float2 bp0 = unpack_bf16(bpbf[jr0 * 128 + 4 * nt + tig]);
            float2 bp1 = unpack_bf16(bpbf[jr1 * 128 + 4 * nt + tig]);
            float v00 = acc[ntl][0] + p0.x + sx0 * p0.y + sya0 * p0.z + sys0 * p0.w + bp0.x;
            float v01 = acc[ntl][1] + p1.x + sx0 * p1.y + sya0 * p1.z + sys0 * p1.w + bp0.y;
            float v10 = acc[ntl][2] + p0.x + sx1 * p0.y + sya1 * p0.z + sys1 * p0.w + bp1.x;
            float v11 = acc[ntl][3] + p1.x + sx1 * p1.y + sya1 * p1.z + sys1 * p1.w + bp1.y;
            v00 = fmaxf(v00, 0.f); v01 = fmaxf(v01, 0.f);
            v10 = fmaxf(v10, 0.f); v11 = fmaxf(v11, 0.f);
            sum0 += v00 + v01; sq0 += v00 * v00 + v01 * v01;
            sum1 += v10 + v11; sq1 += v10 * v10 + v11 * v11;
            int q2 = nt >> 1, off = (nt & 1) * 2;
            H1[4 * q2 + off]     = pack_bf16(v00, v01);
            H1[4 * q2 + off + 1] = pack_bf16(v10, v11);
        }
    }

#pragma unroll
    for (int o = 1; o <= 2; o <<= 1) {
        sum0 += __shfl_xor_sync(0xffffffffu, sum0, o);
        sq0  += __shfl_xor_sync(0xffffffffu, sq0,  o);
        sum1 += __shfl_xor_sync(0xffffffffu, sum1, o);
        sq1  += __shfl_xor_sync(0xffffffffu, sq1,  o);
    }
    float mu0 = sum0 * (1.f / 256.f);
    float rs0 = rsqrtf(sq0 * (1.f / 256.f) - mu0 * mu0 + 1e-5f);
    float mu1 = sum1 * (1.f / 256.f);
    float rs1 = rsqrtf(sq1 * (1.f / 256.f) - mu1 * mu1 + 1e-5f);
#pragma unroll
    for (int q = 0; q < 16; q++) {
#pragma unroll
        for (int e2 = 0; e2 < 2; e2++) {
            int col = 16 * q + 8 * e2 + 2 * tig;
            float2 gb0 = sLgb[col], gb1 = sLgb[col + 1];
#pragma unroll
            for (int e = 0; e < 2; e++) {
                int idx = 4 * q + 2 * e2 + e;
                float2 v = unpack_bf16(H1[idx]);
                float m = e ? mu1 : mu0, rr = e ? rs1 : rs0;
                H1[idx] = pack_bf16((v.x - m) * rr * gb0.x + gb0.y,
                                    (v.y - m) * rr * gb1.x + gb1.y);
            }
        }
    }

    uint32_t H2[32];
#pragma unroll
    for (int h = 0; h < 2; h++) {
        float acc[8][4];
#pragma unroll
        for (int ntl = 0; ntl < 8; ntl++)
#pragma unroll
            for (int q = 0; q < 4; q++) acc[ntl][q] = 0.f;
#pragma unroll
        for (int q = 0; q < 16; q++) {
            uint32_t a0 = H1[4 * q],     a1 = H1[4 * q + 1];
            uint32_t a2 = H1[4 * q + 2], a3 = H1[4 * q + 3];
#pragma unroll
            for (int ntl = 0; ntl < 8; ntl++) {
                int n = (h * 8 + ntl) * 8 + g;
                uint32_t b0 = W2s[n * 132 + 8 * q + tig];
                uint32_t b1 = W2s[n * 132 + 8 * q + 4 + tig];
                mma_bf16(acc[ntl], a0, a1, a2, a3, b0, b1);
            }
        }
#pragma unroll
        for (int ntl = 0; ntl < 8; ntl++) {
            int nt = h * 8 + ntl;
            int c0 = 8 * nt + 2 * tig;
            float v00 = fmaxf(acc[ntl][0] + sB2[c0], 0.f);
            float v01 = fmaxf(acc[ntl][1] + sB2[c0 + 1], 0.f);
            float v10 = fmaxf(acc[ntl][2] + sB2[c0], 0.f);
            float v11 = fmaxf(acc[ntl][3] + sB2[c0 + 1], 0.f);
            int q2 = nt >> 1, off = (nt & 1) * 2;
            H2[4 * q2 + off]     = pack_bf16(v00, v01);
            H2[4 * q2 + off + 1] = pack_bf16(v10, v11);
        }
    }

    uint32_t H3[16];
    {
        float acc[8][4];
#pragma unroll
        for (int ntl = 0; ntl < 8; ntl++)
#pragma unroll
            for (int q = 0; q < 4; q++) acc[ntl][q] = 0.f;
#pragma unroll
        for (int q = 0; q < 8; q++) {
            uint32_t a0 = H2[4 * q],     a1 = H2[4 * q + 1];
            uint32_t a2 = H2[4 * q + 2], a3 = H2[4 * q + 3];
#pragma unroll
            for (int ntl = 0; ntl < 8; ntl++) {
                int n = ntl * 8 + g;
                uint32_t b0 = W3s[n * 68 + 8 * q + tig];
                uint32_t b1 = W3s[n * 68 + 8 * q + 4 + tig];
                mma_bf16(acc[ntl], a0, a1, a2, a3, b0, b1);
            }
        }
#pragma unroll
        for (int nt = 0; nt < 8; nt++) {
            int c0 = 8 * nt + 2 * tig;
            float v00 = fmaxf(acc[nt][0] + sB3[c0], 0.f);
            float v01 = fmaxf(acc[nt][1] + sB3[c0 + 1], 0.f);
            float v10 = fmaxf(acc[nt][2] + sB3[c0], 0.f);
            float v11 = fmaxf(acc[nt][3] + sB3[c0 + 1], 0.f);
            int q2 = nt >> 1, off = (nt & 1) * 2;
            H3[4 * q2 + off]     = pack_bf16(v00, v01);
            H3[4 * q2 + off + 1] = pack_bf16(v10, v11);
        }
    }

    {
        float acc[4][4];
#pragma unroll
        for (int ntl = 0; ntl < 4; ntl++)
#pragma unroll
            for (int q = 0; q < 4; q++) acc[ntl][q] = 0.f;
#pragma unroll
        for (int q = 0; q < 4; q++) {
            uint32_t a0 = H3[4 * q],     a1 = H3[4 * q + 1];
            uint32_t a2 = H3[4 * q + 2], a3 = H3[4 * q + 3];
#pragma unroll
            for (int ntl = 0; ntl < 4; ntl++) {
                int n = ntl * 8 + g;
                uint32_t b0 = W4s[n * 36 + 8 * q + tig];
                uint32_t b1 = W4s[n * 36 + 8 * q + 4 + tig];
                mma_bf16(acc[ntl], a0, a1, a2, a3, b0, b1);
            }
        }
        float p0 = 0.f, p1 = 0.f;
#pragma unroll
        for (int nt = 0; nt < 4; nt++) {
            int c0 = 8 * nt + 2 * tig;
            p0 += fmaxf(acc[nt][0] + sB4[c0], 0.f) * sW5[c0]
                + fmaxf(acc[nt][1] + sB4[c0 + 1], 0.f) * sW5[c0 + 1];
            p1 += fmaxf(acc[nt][2] + sB4[c0], 0.f) * sW5[c0]
                + fmaxf(acc[nt][3] + sB4[c0 + 1], 0.f) * sW5[c0 + 1];
        }
#pragma unroll
        for (int o = 1; o <= 2; o <<= 1) {
            p0 += __shfl_xor_sync(0xffffffffu, p0, o);
            p1 += __shfl_xor_sync(0xffffffffu, p1, o);
        }
        if (tig == 0) {
            float bb = sB5[0];
            out[i * 768 + jr0] = (jr0 == i) ? -1000000000.0f : p0 + bb;
            out[i * 768 + jr1] = (jr1 == i) ? -1000000000.0f : p1 + bb;
        }
    }
}

// ---------------- host launch ------------------------------------------------
extern "C" void kernel_launch(void* const* d_in, const int* in_sizes, int n_in,
                              void* d_out, int out_size)
{
    (void)in_sizes; (void)n_in; (void)out_size;
    const float* features = (const float*)d_in[0];
    const float* boxes    = (const float*)d_in[1];
    const float* in_w     = (const float*)d_in[2];
    const float* in_b     = (const float*)d_in[3];
    const float* out_w    = (const float*)d_in[4];
    const float* out_b    = (const float*)d_in[5];
    const float* w1       = (const float*)d_in[6];
    const float* b1       = (const float*)d_in[7];
    const float* lng      = (const float*)d_in[8];
    const float* lnb      = (const float*)d_in[9];
    const float* w2       = (const float*)d_in[10];
    const float* b2       = (const float*)d_in[11];
    const float* w3       = (const float*)d_in[12];
    const float* b3       = (const float*)d_in[13];
    const float* w4       = (const float*)d_in[14];
    const float* b4       = (const float*)d_in[15];
    const float* w5       = (const float*)d_in[16];
    const float* b5       = (const float*)d_in[17];
    float* out = (float*)d_out;

    void *featbf, *inwbf, *outwbf, *w1abf, *w1bbf, *w1cbf, *w2bf, *w3bf, *w4bf;
    void *qkvbf, *obf, *attbf, *bpbf;
    float* Apb;
    cudaGetSymbolAddress(&featbf, g_feat_bf);
    cudaGetSymbolAddress(&inwbf,  g_inw_bf);
    cudaGetSymbolAddress(&outwbf, g_outw_bf);
    cudaGetSymbolAddress(&w1abf,  g_w1a_bf);
    cudaGetSymbolAddress(&w1bbf,  g_w1b_bf);
    cudaGetSymbolAddress(&w1cbf,  g_w1c_bf);
    cudaGetSymbolAddress(&w2bf,   g_w2_bf);
    cudaGetSymbolAddress(&w3bf,   g_w3_bf);
    cudaGetSymbolAddress(&w4bf,   g_w4_bf);
    cudaGetSymbolAddress(&qkvbf,  g_qkv_bf);
    cudaGetSymbolAddress(&obf,    g_o_bf);
    cudaGetSymbolAddress(&attbf,  g_att_bf);
    cudaGetSymbolAddress(&bpbf,   g_Bp_bf);
    cudaGetSymbolAddress((void**)&Apb, g_Ap);

    cudaFuncSetAttribute(gemm_bf256,
                         cudaFuncAttributeMaxDynamicSharedMemorySize, GEMM_SMEM_BYTES);
    cudaFuncSetAttribute(fused_pairs_reg,
                         cudaFuncAttributeMaxDynamicSharedMemorySize, SMEM_BYTES);

    // 1. fp32 -> bf16 conversions
    convert_pre<<<768, 256>>>(features, in_w, out_w, w1, w2, w3, w4);

    // 2. qkv = feat @ in_w^T + in_b  -> bf16 qkv
    gemm_bf256<<<dim3(6, 6), 256, GEMM_SMEM_BYTES>>>(
        (const uint4*)featbf, (const uint4*)inwbf, in_b,
        nullptr, (uint32_t*)qkvbf, 768);

    // 3. V transpose per head
    build_vT<<<256, 256>>>();

    // 4. flash attention -> o_bf
    attn_flash<<<dim3(6, 8), 256>>>(nullptr);

    // 5. att = o @ out_w^T + out_b -> bf16 att
    gemm_bf256<<<dim3(2, 6), 256, GEMM_SMEM_BYTES>>>(
        (const uint4*)obf, (const uint4*)outwbf, out_b,
        nullptr, (uint32_t*)attbf, 256);

    // 6. Ap = att @ w1a^T + b1 (fp32)
    gemm_bf256<<<dim3(2, 6), 256, GEMM_SMEM_BYTES>>>(
        (const uint4*)attbf, (const uint4*)w1abf, b1,
        Apb, nullptr, 256);

    // 7. Bp = att @ w1b^T (bf16)
    gemm_bf256<<<dim3(2, 6), 256, GEMM_SMEM_BYTES>>>(
        (const uint4*)attbf, (const uint4*)w1bbf, nullptr,
        nullptr, (uint32_t*)bpbf, 256);

    // 8. fused all-pairs MLP
    fused_pairs_reg<<<dim3(6, 768), 256, SMEM_BYTES>>>(
        boxes, w1, Apb,
        (const uint32_t*)attbf, (const uint32_t*)bpbf,
        (const uint4*)w1cbf, (const uint4*)w2bf,
        (const uint4*)w3bf, (const uint4*)w4bf,
        lng, lnb, b2, b3, b4, w5, b5, out);
}